// round 1
// baseline (speedup 1.0000x reference)
#include <cuda_runtime.h>
#include <cstdint>

// ---------------------------------------------------------------------------
// WindowedMultiHeadAttention
//   x:      (16, 3136, 768) fp32
//   w_qkv:  (768, 2304), b_qkv: (2304,)
//   w_proj: (768, 768),  b_proj: (768,)
// H=W=56, WS=14 -> 4x4 windows per image, 256 windows total, 196 tokens each.
// heads=8, d=96. softmax FIRST then divide by sqrt(768).
// ---------------------------------------------------------------------------

#define EMB   768
#define NH    8
#define HD    96
#define NWIN  256      // 16 batches * 16 windows
#define NTOK  196      // 14*14
#define MROWS (NWIN * NTOK)   // 50176
#define QKVC  (3 * EMB)       // 2304

// scratch (device globals: allocation-free)
__device__ float g_Q[NWIN * NH * NTOK * HD];
__device__ float g_K[NWIN * NH * NTOK * HD];
__device__ float g_V[NWIN * NH * NTOK * HD];
__device__ float g_O[MROWS * EMB];

// map window-space row (win*196 + t) -> row index in x (B,3136,C)
__device__ __forceinline__ int map_row(int r) {
    int win = r / NTOK;
    int t   = r - win * NTOK;
    int b   = win >> 4;            // win / 16
    int wr  = win & 15;
    int wh  = wr >> 2;             // window row (0..3)
    int ww  = wr & 3;              // window col (0..3)
    int i   = t / 14;
    int j   = t - i * 14;
    return (b * 56 + wh * 14 + i) * 56 + (ww * 14 + j);
}

// ---------------------------------------------------------------------------
// GEMM 1: qkv = gather(x) @ w_qkv + b_qkv, scattered into Q/K/V [win,h,t,d]
// column c of w_qkv decomposes as c = h*288 + dd*3 + s  (s: 0=q,1=k,2=v)
// BM=BN=128, BK=8, 256 threads, 8x8 per thread.
// ---------------------------------------------------------------------------
__global__ void qkv_gemm_kernel(const float* __restrict__ x,
                                const float* __restrict__ w,
                                const float* __restrict__ bias) {
    __shared__ float As[8][128];
    __shared__ float Bs[8][128];
    __shared__ int   rowp[128];

    const int tid = threadIdx.x;
    const int m0  = blockIdx.y * 128;
    const int n0  = blockIdx.x * 128;

    if (tid < 128) rowp[tid] = map_row(m0 + tid);

    const int arow = tid >> 1;
    const int acol = (tid & 1) * 4;
    const int brow = tid >> 5;
    const int bcol = (tid & 31) * 4;

    const int ty = tid >> 4;
    const int tx = tid & 15;

    float acc[8][8];
#pragma unroll
    for (int i = 0; i < 8; i++)
#pragma unroll
        for (int j = 0; j < 8; j++) acc[i][j] = 0.f;

    __syncthreads();

    for (int k0 = 0; k0 < EMB; k0 += 8) {
        float4 av = *(const float4*)(x + (size_t)rowp[arow] * EMB + k0 + acol);
        As[acol + 0][arow] = av.x;
        As[acol + 1][arow] = av.y;
        As[acol + 2][arow] = av.z;
        As[acol + 3][arow] = av.w;
        float4 bv = *(const float4*)(w + (size_t)(k0 + brow) * QKVC + n0 + bcol);
        *(float4*)&Bs[brow][bcol] = bv;
        __syncthreads();
#pragma unroll
        for (int k = 0; k < 8; k++) {
            float4 a0 = *(const float4*)&As[k][ty * 8];
            float4 a1 = *(const float4*)&As[k][ty * 8 + 4];
            float4 b0 = *(const float4*)&Bs[k][tx * 8];
            float4 b1 = *(const float4*)&Bs[k][tx * 8 + 4];
            float a[8] = {a0.x, a0.y, a0.z, a0.w, a1.x, a1.y, a1.z, a1.w};
            float b[8] = {b0.x, b0.y, b0.z, b0.w, b1.x, b1.y, b1.z, b1.w};
#pragma unroll
            for (int i = 0; i < 8; i++)
#pragma unroll
                for (int j = 0; j < 8; j++) acc[i][j] += a[i] * b[j];
        }
        __syncthreads();
    }

    // epilogue: scatter into Q/K/V
#pragma unroll
    for (int i = 0; i < 8; i++) {
        const int r   = m0 + ty * 8 + i;
        const int win = r / NTOK;
        const int t   = r - win * NTOK;
#pragma unroll
        for (int j = 0; j < 8; j++) {
            const int c  = n0 + tx * 8 + j;
            float v      = acc[i][j] + bias[c];
            const int h  = c / 288;
            const int rm = c - h * 288;
            const int dd = rm / 3;
            const int s  = rm - dd * 3;
            const size_t dst = (((size_t)(win * NH + h)) * NTOK + t) * HD + dd;
            if (s == 0)      g_Q[dst] = v;
            else if (s == 1) g_K[dst] = v;
            else             g_V[dst] = v;
        }
    }
}

// ---------------------------------------------------------------------------
// Attention: one CTA per (win, head).  224 threads, thread t owns query row t.
// smem buffer (196x96 f32 = 75264B) holds K during pass 1, V during pass 2.
// Exact softmax, scale 1/sqrt(768) applied AFTER softmax (faithful to ref).
// ---------------------------------------------------------------------------
__global__ void __launch_bounds__(224)
attn_kernel() {
    extern __shared__ float buf[];   // 196*96 floats
    const int wh  = blockIdx.x;      // win*8 + h
    const int tid = threadIdx.x;
    const size_t base = (size_t)wh * NTOK * HD;

    // stage K
    {
        const float4* src = (const float4*)(g_K + base);
        float4* dst = (float4*)buf;
#pragma unroll
        for (int i = 0; i < 21; i++) dst[tid + i * 224] = src[tid + i * 224];
    }
    __syncthreads();

    const int t = tid;
    float p[NTOK];               // per-row scores (local mem)
    float m = -1e30f, Z = 0.f;

    if (t < NTOK) {
        float4 q[24];
        const float4* qp = (const float4*)(g_Q + base + (size_t)t * HD);
#pragma unroll
        for (int i = 0; i < 24; i++) q[i] = qp[i];

#pragma unroll 1
        for (int k = 0; k < NTOK; k++) {
            const float4* kk = (const float4*)(buf + k * HD);
            float s = 0.f;
#pragma unroll
            for (int i = 0; i < 24; i++) {
                float4 kv = kk[i];
                s += q[i].x * kv.x + q[i].y * kv.y + q[i].z * kv.z + q[i].w * kv.w;
            }
            p[k] = s;
            m = fmaxf(m, s);
        }
#pragma unroll 1
        for (int k = 0; k < NTOK; k++) {
            float e = __expf(p[k] - m);
            p[k] = e;
            Z += e;
        }
    }
    __syncthreads();   // K no longer needed

    // stage V
    {
        const float4* src = (const float4*)(g_V + base);
        float4* dst = (float4*)buf;
#pragma unroll
        for (int i = 0; i < 21; i++) dst[tid + i * 224] = src[tid + i * 224];
    }
    __syncthreads();

    if (t < NTOK) {
        const float inv = 1.0f / (Z * 27.712812921102035f);  // / (Z * sqrt(768))
        float4 o[24];
#pragma unroll
        for (int i = 0; i < 24; i++) o[i] = make_float4(0.f, 0.f, 0.f, 0.f);

#pragma unroll 1
        for (int k = 0; k < NTOK; k++) {
            const float w = p[k] * inv;
            const float4* vv = (const float4*)(buf + k * HD);
#pragma unroll
            for (int i = 0; i < 24; i++) {
                float4 v = vv[i];
                o[i].x += w * v.x;
                o[i].y += w * v.y;
                o[i].z += w * v.z;
                o[i].w += w * v.w;
            }
        }
        const int win = wh >> 3;
        const int h   = wh & 7;
        float4* op = (float4*)(g_O + ((size_t)(win * NTOK + t)) * EMB + h * HD);
#pragma unroll
        for (int i = 0; i < 24; i++) op[i] = o[i];
    }
}

// ---------------------------------------------------------------------------
// GEMM 3: out = window_reverse(O @ w_proj + b_proj) + x   -> d_out
// ---------------------------------------------------------------------------
__global__ void proj_gemm_kernel(const float* __restrict__ x,
                                 const float* __restrict__ w,
                                 const float* __restrict__ bias,
                                 float* __restrict__ out) {
    __shared__ float As[8][128];
    __shared__ float Bs[8][128];

    const int tid = threadIdx.x;
    const int m0  = blockIdx.y * 128;
    const int n0  = blockIdx.x * 128;

    const int arow = tid >> 1;
    const int acol = (tid & 1) * 4;
    const int brow = tid >> 5;
    const int bcol = (tid & 31) * 4;

    const int ty = tid >> 4;
    const int tx = tid & 15;

    float acc[8][8];
#pragma unroll
    for (int i = 0; i < 8; i++)
#pragma unroll
        for (int j = 0; j < 8; j++) acc[i][j] = 0.f;

    for (int k0 = 0; k0 < EMB; k0 += 8) {
        float4 av = *(const float4*)(g_O + (size_t)(m0 + arow) * EMB + k0 + acol);
        As[acol + 0][arow] = av.x;
        As[acol + 1][arow] = av.y;
        As[acol + 2][arow] = av.z;
        As[acol + 3][arow] = av.w;
        float4 bv = *(const float4*)(w + (size_t)(k0 + brow) * EMB + n0 + bcol);
        *(float4*)&Bs[brow][bcol] = bv;
        __syncthreads();
#pragma unroll
        for (int k = 0; k < 8; k++) {
            float4 a0 = *(const float4*)&As[k][ty * 8];
            float4 a1 = *(const float4*)&As[k][ty * 8 + 4];
            float4 b0 = *(const float4*)&Bs[k][tx * 8];
            float4 b1 = *(const float4*)&Bs[k][tx * 8 + 4];
            float a[8] = {a0.x, a0.y, a0.z, a0.w, a1.x, a1.y, a1.z, a1.w};
            float b[8] = {b0.x, b0.y, b0.z, b0.w, b1.x, b1.y, b1.z, b1.w};
#pragma unroll
            for (int i = 0; i < 8; i++)
#pragma unroll
                for (int j = 0; j < 8; j++) acc[i][j] += a[i] * b[j];
        }
        __syncthreads();
    }

    // epilogue: window reverse + bias + residual
#pragma unroll
    for (int i = 0; i < 8; i++) {
        const int r  = m0 + ty * 8 + i;
        const int xr = map_row(r);
        // xr is row within image; full row index includes batch already in map_row
#pragma unroll
        for (int j = 0; j < 8; j++) {
            const int c = n0 + tx * 8 + j;
            const size_t idx = (size_t)xr * EMB + c;
            out[idx] = acc[i][j] + bias[c] + x[idx];
        }
    }
}

// ---------------------------------------------------------------------------
extern "C" void kernel_launch(void* const* d_in, const int* in_sizes, int n_in,
                              void* d_out, int out_size) {
    const float* x      = (const float*)d_in[0];
    const float* w_qkv  = (const float*)d_in[1];
    const float* b_qkv  = (const float*)d_in[2];
    const float* w_proj = (const float*)d_in[3];
    const float* b_proj = (const float*)d_in[4];
    float* out = (float*)d_out;

    // GEMM1: M=50176, N=2304 -> grid (18, 392)
    dim3 g1(QKVC / 128, MROWS / 128);
    qkv_gemm_kernel<<<g1, 256>>>(x, w_qkv, b_qkv);

    // attention: 2048 CTAs, 75264B dynamic smem
    const int smem = NTOK * HD * sizeof(float);
    cudaFuncSetAttribute(attn_kernel, cudaFuncAttributeMaxDynamicSharedMemorySize, smem);
    attn_kernel<<<NWIN * NH, 224, smem>>>();

    // GEMM3: M=50176, N=768 -> grid (6, 392)
    dim3 g3(EMB / 128, MROWS / 128);
    proj_gemm_kernel<<<g3, 256>>>(x, w_proj, b_proj, out);
}

// round 2
// speedup vs baseline: 1.5648x; 1.5648x over previous
#include <cuda_runtime.h>
#include <cstdint>

// ---------------------------------------------------------------------------
// WindowedMultiHeadAttention — tf32 tensor-core GEMMs + SIMT attention
// ---------------------------------------------------------------------------

#define EMB   768
#define NH    8
#define HD    96
#define NWIN  256      // 16 batches * 16 windows
#define NTOK  196      // 14*14
#define MROWS (NWIN * NTOK)   // 50176
#define QKVC  (3 * EMB)       // 2304

// scratch (device globals: allocation-free)
__device__ float g_Q[NWIN * NH * NTOK * HD];
__device__ float g_K[NWIN * NH * NTOK * HD];
__device__ float g_V[NWIN * NH * NTOK * HD];
__device__ float g_O[MROWS * EMB];

// map window-space row (win*196 + t) -> row index in x (B,3136,C)
__device__ __forceinline__ int map_row(int r) {
    int win = r / NTOK;
    int t   = r - win * NTOK;
    int b   = win >> 4;
    int wr  = win & 15;
    int wh  = wr >> 2;
    int ww  = wr & 3;
    int i   = t / 14;
    int j   = t - i * 14;
    return (b * 56 + wh * 14 + i) * 56 + (ww * 14 + j);
}

__device__ __forceinline__ uint32_t f2tf(float v) {
    uint32_t t;
    asm("cvt.rna.tf32.f32 %0, %1;" : "=r"(t) : "f"(v));
    return t;
}

__device__ __forceinline__ void mma_tf32(float* d, const uint32_t* a, const uint32_t* b) {
    asm volatile(
        "mma.sync.aligned.m16n8k8.row.col.f32.tf32.tf32.f32 "
        "{%0,%1,%2,%3}, {%4,%5,%6,%7}, {%8,%9}, {%0,%1,%2,%3};"
        : "+f"(d[0]), "+f"(d[1]), "+f"(d[2]), "+f"(d[3])
        : "r"(a[0]), "r"(a[1]), "r"(a[2]), "r"(a[3]), "r"(b[0]), "r"(b[1]));
}

// smem strides (banks: A frag reads (tig*132+row)&31 = 4*tig+row -> distinct;
// B frag reads (k*136+n)&31 = 8*k+n -> distinct)
#define ASTRIDE 132
#define BSTRIDE 136

// ---------------------------------------------------------------------------
// GEMM 1: qkv = gather(x) @ w_qkv + b_qkv, scattered into Q/K/V [win,h,t,d]
// ---------------------------------------------------------------------------
__global__ void __launch_bounds__(256)
qkv_gemm_tc(const float* __restrict__ x,
            const float* __restrict__ w,
            const float* __restrict__ bias) {
    __shared__ uint32_t As[2 * 16 * ASTRIDE];
    __shared__ uint32_t Bs[2 * 16 * BSTRIDE];
    __shared__ int rowp[128];

    const int tid = threadIdx.x;
    const int m0 = blockIdx.y * 128;
    const int n0 = blockIdx.x * 128;

    if (tid < 128) rowp[tid] = map_row(m0 + tid);
    __syncthreads();

    // A load coords: thread -> (m, k-half)
    const int lm = tid & 127;
    const int kh = (tid >> 7) * 8;
    const size_t arow = (size_t)rowp[lm] * EMB;
    // B load coords: thread -> (k-row, n-quad)
    const int kb = tid >> 4;
    const int nq = (tid & 15) * 4;

    const int w_id = tid >> 5, lane = tid & 31;
    const int wm = (w_id >> 2) * 64;        // warp row offset
    const int wn = (w_id & 3) * 32;         // warp col offset
    const int gid = lane >> 2, tig = lane & 3;

    float acc[4][4][4];
#pragma unroll
    for (int i = 0; i < 4; i++)
#pragma unroll
        for (int j = 0; j < 4; j++)
#pragma unroll
            for (int k = 0; k < 4; k++) acc[i][j][k] = 0.f;

    float4 ra0, ra1, rb0, rb1;

#define LOAD_GLOBAL(K0)                                                        \
    do {                                                                       \
        ra0 = *(const float4*)(x + arow + (K0) + kh);                          \
        ra1 = *(const float4*)(x + arow + (K0) + kh + 4);                      \
        rb0 = *(const float4*)(w + (size_t)((K0) + kb) * QKVC + n0 + nq);      \
        rb1 = *(const float4*)(w + (size_t)((K0) + kb) * QKVC + n0 + nq + 64); \
    } while (0)

#define STORE_SMEM(BUF)                                                        \
    do {                                                                       \
        uint32_t* ap = As + (BUF) * 16 * ASTRIDE;                              \
        ap[(kh + 0) * ASTRIDE + lm] = f2tf(ra0.x);                             \
        ap[(kh + 1) * ASTRIDE + lm] = f2tf(ra0.y);                             \
        ap[(kh + 2) * ASTRIDE + lm] = f2tf(ra0.z);                             \
        ap[(kh + 3) * ASTRIDE + lm] = f2tf(ra0.w);                             \
        ap[(kh + 4) * ASTRIDE + lm] = f2tf(ra1.x);                             \
        ap[(kh + 5) * ASTRIDE + lm] = f2tf(ra1.y);                             \
        ap[(kh + 6) * ASTRIDE + lm] = f2tf(ra1.z);                             \
        ap[(kh + 7) * ASTRIDE + lm] = f2tf(ra1.w);                             \
        uint32_t* bp = Bs + (BUF) * 16 * BSTRIDE + kb * BSTRIDE;               \
        uint4 t0 = make_uint4(f2tf(rb0.x), f2tf(rb0.y), f2tf(rb0.z), f2tf(rb0.w)); \
        uint4 t1 = make_uint4(f2tf(rb1.x), f2tf(rb1.y), f2tf(rb1.z), f2tf(rb1.w)); \
        *(uint4*)(bp + nq) = t0;                                               \
        *(uint4*)(bp + nq + 64) = t1;                                          \
    } while (0)

#define COMPUTE(BUF)                                                           \
    do {                                                                       \
        const uint32_t* ap = As + (BUF) * 16 * ASTRIDE;                        \
        const uint32_t* bp = Bs + (BUF) * 16 * BSTRIDE;                        \
        _Pragma("unroll")                                                      \
        for (int kk = 0; kk < 16; kk += 8) {                                   \
            uint32_t af[4][4], bf[4][2];                                       \
            _Pragma("unroll")                                                  \
            for (int mf = 0; mf < 4; mf++) {                                   \
                int r = wm + mf * 16 + gid;                                    \
                af[mf][0] = ap[(kk + tig) * ASTRIDE + r];                      \
                af[mf][1] = ap[(kk + tig) * ASTRIDE + r + 8];                  \
                af[mf][2] = ap[(kk + 4 + tig) * ASTRIDE + r];                  \
                af[mf][3] = ap[(kk + 4 + tig) * ASTRIDE + r + 8];              \
            }                                                                  \
            _Pragma("unroll")                                                  \
            for (int nf = 0; nf < 4; nf++) {                                   \
                int c = wn + nf * 8 + gid;                                     \
                bf[nf][0] = bp[(kk + tig) * BSTRIDE + c];                      \
                bf[nf][1] = bp[(kk + 4 + tig) * BSTRIDE + c];                  \
            }                                                                  \
            _Pragma("unroll")                                                  \
            for (int mf = 0; mf < 4; mf++)                                     \
                _Pragma("unroll")                                              \
                for (int nf = 0; nf < 4; nf++)                                 \
                    mma_tf32(acc[mf][nf], af[mf], bf[nf]);                     \
        }                                                                      \
    } while (0)

    LOAD_GLOBAL(0);
    STORE_SMEM(0);
    __syncthreads();

    int buf = 0;
#pragma unroll 1
    for (int it = 0; it < EMB / 16; ++it) {
        if (it + 1 < EMB / 16) LOAD_GLOBAL((it + 1) * 16);
        COMPUTE(buf);
        if (it + 1 < EMB / 16) {
            STORE_SMEM(buf ^ 1);
            buf ^= 1;
            __syncthreads();
        }
    }

    // epilogue: bias + scatter into Q/K/V
#pragma unroll
    for (int mf = 0; mf < 4; mf++) {
#pragma unroll
        for (int i2 = 0; i2 < 2; i2++) {
            const int r = m0 + wm + mf * 16 + gid + i2 * 8;
            const int win = r / NTOK;
            const int t = r - win * NTOK;
#pragma unroll
            for (int nf = 0; nf < 4; nf++) {
#pragma unroll
                for (int j2 = 0; j2 < 2; j2++) {
                    const int c = n0 + wn + nf * 8 + tig * 2 + j2;
                    float v = acc[mf][nf][i2 * 2 + j2] + bias[c];
                    const int h = c / 288;
                    const int rm = c - h * 288;
                    const int dd = rm / 3;
                    const int s = rm - dd * 3;
                    const size_t dst = (((size_t)(win * NH + h)) * NTOK + t) * HD + dd;
                    if (s == 0)      g_Q[dst] = v;
                    else if (s == 1) g_K[dst] = v;
                    else             g_V[dst] = v;
                }
            }
        }
    }
#undef LOAD_GLOBAL
#undef STORE_SMEM
#undef COMPUTE
}

// ---------------------------------------------------------------------------
// GEMM 3: out = window_reverse(g_O @ w_proj + b_proj) + x
// ---------------------------------------------------------------------------
__global__ void __launch_bounds__(256)
proj_gemm_tc(const float* __restrict__ x,
             const float* __restrict__ w,
             const float* __restrict__ bias,
             float* __restrict__ out) {
    __shared__ uint32_t As[2 * 16 * ASTRIDE];
    __shared__ uint32_t Bs[2 * 16 * BSTRIDE];

    const int tid = threadIdx.x;
    const int m0 = blockIdx.y * 128;
    const int n0 = blockIdx.x * 128;

    const int lm = tid & 127;
    const int kh = (tid >> 7) * 8;
    const size_t arow = (size_t)(m0 + lm) * EMB;
    const int kb = tid >> 4;
    const int nq = (tid & 15) * 4;

    const int w_id = tid >> 5, lane = tid & 31;
    const int wm = (w_id >> 2) * 64;
    const int wn = (w_id & 3) * 32;
    const int gid = lane >> 2, tig = lane & 3;

    float acc[4][4][4];
#pragma unroll
    for (int i = 0; i < 4; i++)
#pragma unroll
        for (int j = 0; j < 4; j++)
#pragma unroll
            for (int k = 0; k < 4; k++) acc[i][j][k] = 0.f;

    float4 ra0, ra1, rb0, rb1;

#define LOAD_GLOBAL(K0)                                                        \
    do {                                                                       \
        ra0 = *(const float4*)(g_O + arow + (K0) + kh);                        \
        ra1 = *(const float4*)(g_O + arow + (K0) + kh + 4);                    \
        rb0 = *(const float4*)(w + (size_t)((K0) + kb) * EMB + n0 + nq);       \
        rb1 = *(const float4*)(w + (size_t)((K0) + kb) * EMB + n0 + nq + 64);  \
    } while (0)

#define STORE_SMEM(BUF)                                                        \
    do {                                                                       \
        uint32_t* ap = As + (BUF) * 16 * ASTRIDE;                              \
        ap[(kh + 0) * ASTRIDE + lm] = f2tf(ra0.x);                             \
        ap[(kh + 1) * ASTRIDE + lm] = f2tf(ra0.y);                             \
        ap[(kh + 2) * ASTRIDE + lm] = f2tf(ra0.z);                             \
        ap[(kh + 3) * ASTRIDE + lm] = f2tf(ra0.w);                             \
        ap[(kh + 4) * ASTRIDE + lm] = f2tf(ra1.x);                             \
        ap[(kh + 5) * ASTRIDE + lm] = f2tf(ra1.y);                             \
        ap[(kh + 6) * ASTRIDE + lm] = f2tf(ra1.z);                             \
        ap[(kh + 7) * ASTRIDE + lm] = f2tf(ra1.w);                             \
        uint32_t* bp = Bs + (BUF) * 16 * BSTRIDE + kb * BSTRIDE;               \
        uint4 t0 = make_uint4(f2tf(rb0.x), f2tf(rb0.y), f2tf(rb0.z), f2tf(rb0.w)); \
        uint4 t1 = make_uint4(f2tf(rb1.x), f2tf(rb1.y), f2tf(rb1.z), f2tf(rb1.w)); \
        *(uint4*)(bp + nq) = t0;                                               \
        *(uint4*)(bp + nq + 64) = t1;                                          \
    } while (0)

#define COMPUTE(BUF)                                                           \
    do {                                                                       \
        const uint32_t* ap = As + (BUF) * 16 * ASTRIDE;                        \
        const uint32_t* bp = Bs + (BUF) * 16 * BSTRIDE;                        \
        _Pragma("unroll")                                                      \
        for (int kk = 0; kk < 16; kk += 8) {                                   \
            uint32_t af[4][4], bf[4][2];                                       \
            _Pragma("unroll")                                                  \
            for (int mf = 0; mf < 4; mf++) {                                   \
                int r = wm + mf * 16 + gid;                                    \
                af[mf][0] = ap[(kk + tig) * ASTRIDE + r];                      \
                af[mf][1] = ap[(kk + tig) * ASTRIDE + r + 8];                  \
                af[mf][2] = ap[(kk + 4 + tig) * ASTRIDE + r];                  \
                af[mf][3] = ap[(kk + 4 + tig) * ASTRIDE + r + 8];              \
            }                                                                  \
            _Pragma("unroll")                                                  \
            for (int nf = 0; nf < 4; nf++) {                                   \
                int c = wn + nf * 8 + gid;                                     \
                bf[nf][0] = bp[(kk + tig) * BSTRIDE + c];                      \
                bf[nf][1] = bp[(kk + 4 + tig) * BSTRIDE + c];                  \
            }                                                                  \
            _Pragma("unroll")                                                  \
            for (int mf = 0; mf < 4; mf++)                                     \
                _Pragma("unroll")                                              \
                for (int nf = 0; nf < 4; nf++)                                 \
                    mma_tf32(acc[mf][nf], af[mf], bf[nf]);                     \
        }                                                                      \
    } while (0)

    LOAD_GLOBAL(0);
    STORE_SMEM(0);
    __syncthreads();

    int buf = 0;
#pragma unroll 1
    for (int it = 0; it < EMB / 16; ++it) {
        if (it + 1 < EMB / 16) LOAD_GLOBAL((it + 1) * 16);
        COMPUTE(buf);
        if (it + 1 < EMB / 16) {
            STORE_SMEM(buf ^ 1);
            buf ^= 1;
            __syncthreads();
        }
    }

    // epilogue: window reverse + bias + residual
#pragma unroll
    for (int mf = 0; mf < 4; mf++) {
#pragma unroll
        for (int i2 = 0; i2 < 2; i2++) {
            const int r = m0 + wm + mf * 16 + gid + i2 * 8;
            const int xr = map_row(r);
#pragma unroll
            for (int nf = 0; nf < 4; nf++) {
#pragma unroll
                for (int j2 = 0; j2 < 2; j2++) {
                    const int c = n0 + wn + nf * 8 + tig * 2 + j2;
                    const size_t idx = (size_t)xr * EMB + c;
                    out[idx] = acc[mf][nf][i2 * 2 + j2] + bias[c] + x[idx];
                }
            }
        }
    }
#undef LOAD_GLOBAL
#undef STORE_SMEM
#undef COMPUTE
}

// ---------------------------------------------------------------------------
// Attention: one CTA per (win, head). 224 threads, thread t owns query row t.
// ---------------------------------------------------------------------------
__global__ void __launch_bounds__(224)
attn_kernel() {
    extern __shared__ float buf[];   // 196*96 floats
    const int wh  = blockIdx.x;      // win*8 + h
    const int tid = threadIdx.x;
    const size_t base = (size_t)wh * NTOK * HD;

    // stage K
    {
        const float4* src = (const float4*)(g_K + base);
        float4* dst = (float4*)buf;
#pragma unroll
        for (int i = 0; i < 21; i++) dst[tid + i * 224] = src[tid + i * 224];
    }
    __syncthreads();

    const int t = tid;
    float p[NTOK];
    float m = -1e30f, Z = 0.f;

    if (t < NTOK) {
        float4 q[24];
        const float4* qp = (const float4*)(g_Q + base + (size_t)t * HD);
#pragma unroll
        for (int i = 0; i < 24; i++) q[i] = qp[i];

#pragma unroll 1
        for (int k = 0; k < NTOK; k++) {
            const float4* kk = (const float4*)(buf + k * HD);
            float s = 0.f;
#pragma unroll
            for (int i = 0; i < 24; i++) {
                float4 kv = kk[i];
                s += q[i].x * kv.x + q[i].y * kv.y + q[i].z * kv.z + q[i].w * kv.w;
            }
            p[k] = s;
            m = fmaxf(m, s);
        }
#pragma unroll 1
        for (int k = 0; k < NTOK; k++) {
            float e = __expf(p[k] - m);
            p[k] = e;
            Z += e;
        }
    }
    __syncthreads();

    // stage V
    {
        const float4* src = (const float4*)(g_V + base);
        float4* dst = (float4*)buf;
#pragma unroll
        for (int i = 0; i < 21; i++) dst[tid + i * 224] = src[tid + i * 224];
    }
    __syncthreads();

    if (t < NTOK) {
        const float inv = 1.0f / (Z * 27.712812921102035f);
        float4 o[24];
#pragma unroll
        for (int i = 0; i < 24; i++) o[i] = make_float4(0.f, 0.f, 0.f, 0.f);

#pragma unroll 1
        for (int k = 0; k < NTOK; k++) {
            const float w = p[k] * inv;
            const float4* vv = (const float4*)(buf + k * HD);
#pragma unroll
            for (int i = 0; i < 24; i++) {
                float4 v = vv[i];
                o[i].x += w * v.x;
                o[i].y += w * v.y;
                o[i].z += w * v.z;
                o[i].w += w * v.w;
            }
        }
        const int win = wh >> 3;
        const int h   = wh & 7;
        float4* op = (float4*)(g_O + ((size_t)(win * NTOK + t)) * EMB + h * HD);
#pragma unroll
        for (int i = 0; i < 24; i++) op[i] = o[i];
    }
}

// ---------------------------------------------------------------------------
extern "C" void kernel_launch(void* const* d_in, const int* in_sizes, int n_in,
                              void* d_out, int out_size) {
    const float* x      = (const float*)d_in[0];
    const float* w_qkv  = (const float*)d_in[1];
    const float* b_qkv  = (const float*)d_in[2];
    const float* w_proj = (const float*)d_in[3];
    const float* b_proj = (const float*)d_in[4];
    float* out = (float*)d_out;

    dim3 g1(QKVC / 128, MROWS / 128);
    qkv_gemm_tc<<<g1, 256>>>(x, w_qkv, b_qkv);

    const int smem = NTOK * HD * sizeof(float);
    cudaFuncSetAttribute(attn_kernel, cudaFuncAttributeMaxDynamicSharedMemorySize, smem);
    attn_kernel<<<NWIN * NH, 224, smem>>>();

    dim3 g3(EMB / 128, MROWS / 128);
    proj_gemm_tc<<<g3, 256>>>(x, w_proj, b_proj, out);
}

// round 3
// speedup vs baseline: 2.4534x; 1.5679x over previous
#include <cuda_runtime.h>
#include <cuda_bf16.h>
#include <cstdint>

// ---------------------------------------------------------------------------
// WindowedMultiHeadAttention — bf16 mma.sync GEMMs (ldmatrix + cp.async) +
// fp32 SIMT attention.
// ---------------------------------------------------------------------------

#define EMB   768
#define NH    8
#define HD    96
#define NWIN  256
#define NTOK  196
#define MROWS (NWIN * NTOK)   // 50176
#define QKVC  (3 * EMB)       // 2304

// scratch (device globals: allocation-free)
__device__ float g_Q[NWIN * NH * NTOK * HD];
__device__ float g_K[NWIN * NH * NTOK * HD];
__device__ float g_V[NWIN * NH * NTOK * HD];
__device__ __nv_bfloat16 g_A1[MROWS * EMB];   // window-gathered x, bf16
__device__ __nv_bfloat16 g_W1[QKVC * EMB];    // w_qkv transposed [c][k], bf16
__device__ __nv_bfloat16 g_W2[EMB * EMB];     // w_proj transposed [c][k], bf16
__device__ __nv_bfloat16 g_Ob[MROWS * EMB];   // attention output, bf16

// map window-space row (win*196 + t) -> row index in x (B,3136,C)
__device__ __forceinline__ int map_row(int r) {
    int win = r / NTOK;
    int t   = r - win * NTOK;
    int b   = win >> 4;
    int wr  = win & 15;
    int wh  = wr >> 2;
    int ww  = wr & 3;
    int i   = t / 14;
    int j   = t - i * 14;
    return (b * 56 + wh * 14 + i) * 56 + (ww * 14 + j);
}

__device__ __forceinline__ uint32_t pk(float x, float y) {
    __nv_bfloat162 h = __floats2bfloat162_rn(x, y);
    return *reinterpret_cast<uint32_t*>(&h);
}

__device__ __forceinline__ void cp16(uint32_t dst, const void* src) {
    asm volatile("cp.async.cg.shared.global [%0], [%1], 16;" :: "r"(dst), "l"(src));
}
__device__ __forceinline__ void cp_commit() {
    asm volatile("cp.async.commit_group;");
}

__device__ __forceinline__ void ldsm4(uint32_t* r, uint32_t addr) {
    asm volatile("ldmatrix.sync.aligned.m8n8.x4.shared.b16 {%0,%1,%2,%3}, [%4];"
                 : "=r"(r[0]), "=r"(r[1]), "=r"(r[2]), "=r"(r[3]) : "r"(addr));
}

__device__ __forceinline__ void mma_bf16(float* d, const uint32_t* a, uint32_t b0, uint32_t b1) {
    asm volatile(
        "mma.sync.aligned.m16n8k16.row.col.f32.bf16.bf16.f32 "
        "{%0,%1,%2,%3}, {%4,%5,%6,%7}, {%8,%9}, {%0,%1,%2,%3};"
        : "+f"(d[0]), "+f"(d[1]), "+f"(d[2]), "+f"(d[3])
        : "r"(a[0]), "r"(a[1]), "r"(a[2]), "r"(a[3]), "r"(b0), "r"(b1));
}

// ---------------------------------------------------------------------------
// prep kernels: gather/convert/transpose to bf16
// ---------------------------------------------------------------------------
__global__ void conv_x_kernel(const float* __restrict__ x) {
    int g  = blockIdx.x * 256 + threadIdx.x;     // MROWS*96 threads
    int r  = g / 96;
    int kc = (g - r * 96) * 8;
    const float* s = x + (size_t)map_row(r) * EMB + kc;
    float4 v0 = *(const float4*)s;
    float4 v1 = *(const float4*)(s + 4);
    uint4 u;
    u.x = pk(v0.x, v0.y); u.y = pk(v0.z, v0.w);
    u.z = pk(v1.x, v1.y); u.w = pk(v1.z, v1.w);
    *(uint4*)(g_A1 + (size_t)r * EMB + kc) = u;
}

__global__ void conv_w1_kernel(const float* __restrict__ w) {
    int g  = blockIdx.x * 256 + threadIdx.x;     // QKVC*96 threads
    int c  = g / 96;
    int k0 = (g - c * 96) * 8;
    float v[8];
#pragma unroll
    for (int i = 0; i < 8; i++) v[i] = w[(size_t)(k0 + i) * QKVC + c];
    uint4 u;
    u.x = pk(v[0], v[1]); u.y = pk(v[2], v[3]);
    u.z = pk(v[4], v[5]); u.w = pk(v[6], v[7]);
    *(uint4*)(g_W1 + (size_t)c * EMB + k0) = u;
}

__global__ void conv_w2_kernel(const float* __restrict__ w) {
    int g  = blockIdx.x * 256 + threadIdx.x;     // EMB*96 threads
    int c  = g / 96;
    int k0 = (g - c * 96) * 8;
    float v[8];
#pragma unroll
    for (int i = 0; i < 8; i++) v[i] = w[(size_t)(k0 + i) * EMB + c];
    uint4 u;
    u.x = pk(v[0], v[1]); u.y = pk(v[2], v[3]);
    u.z = pk(v[4], v[5]); u.w = pk(v[6], v[7]);
    *(uint4*)(g_W2 + (size_t)c * EMB + k0) = u;
}

// ---------------------------------------------------------------------------
// Shared bf16 GEMM mainloop: C[128m x 128n] += A[m][k] * B[n][k]^T, K=768.
// A, B both bf16 K-major with row stride EMB. 256 threads, 8 warps (64x32).
// 3-stage cp.async pipeline, BK=32, xor-swizzled smem.
// smem unit = 16B. stage: A units [0,512), B units [512,1024).
// phys(row, kc) = row*4 + (kc ^ ((row>>1)&3))
// ---------------------------------------------------------------------------
__device__ __forceinline__ void gemm_main(const __nv_bfloat16* __restrict__ Asrc,
                                          const __nv_bfloat16* __restrict__ Bsrc,
                                          int m0, int n0,
                                          float (&acc)[4][4][4]) {
    __shared__ uint4 smem[3 * 1024];
    const int tid = threadIdx.x;
    const uint32_t sbase = (uint32_t)__cvta_generic_to_shared(smem);

#pragma unroll
    for (int i = 0; i < 4; i++)
#pragma unroll
        for (int j = 0; j < 4; j++)
#pragma unroll
            for (int q = 0; q < 4; q++) acc[i][j][q] = 0.f;

    // staging coords: thread -> (row, 2 kc units)
    const int srow = tid >> 1;
    const int skc0 = (tid & 1) * 2;

    // compute coords
    const int wid = tid >> 5, lane = tid & 31;
    const int wm = (wid >> 2) * 64, wn = (wid & 3) * 32;
    const int lr = lane & 15, khalf = lane >> 4;

#define PHYS(stage, half, row, kc) \
    (sbase + (uint32_t)(((stage) * 1024 + (half) * 512 + (row) * 4 + ((kc) ^ (((row) >> 1) & 3))) * 16))

#define ISSUE(stage, k0)                                                           \
    do {                                                                           \
        _Pragma("unroll")                                                          \
        for (int i = 0; i < 2; i++) {                                              \
            int kc = skc0 + i;                                                     \
            cp16(PHYS(stage, 0, srow, kc), Asrc + (size_t)(m0 + srow) * EMB + (k0) + kc * 8); \
            cp16(PHYS(stage, 1, srow, kc), Bsrc + (size_t)(n0 + srow) * EMB + (k0) + kc * 8); \
        }                                                                          \
    } while (0)

    ISSUE(0, 0); cp_commit();
    ISSUE(1, 32); cp_commit();

#pragma unroll 1
    for (int it = 0; it < 24; it++) {
        asm volatile("cp.async.wait_group 1;");
        __syncthreads();
        if (it + 2 < 24) {
            int ns = (it + 2) % 3;
            ISSUE(ns, (it + 2) * 32);
        }
        cp_commit();
        const int st = it % 3;
#pragma unroll
        for (int kki = 0; kki < 2; kki++) {
            uint32_t a[4][4], b[2][4];
            const int kc = kki * 2 + khalf;
#pragma unroll
            for (int mf = 0; mf < 4; mf++)
                ldsm4(a[mf], PHYS(st, 0, wm + mf * 16 + lr, kc));
#pragma unroll
            for (int nt = 0; nt < 2; nt++)
                ldsm4(b[nt], PHYS(st, 1, wn + nt * 16 + lr, kc));
#pragma unroll
            for (int mf = 0; mf < 4; mf++)
#pragma unroll
                for (int nt = 0; nt < 2; nt++)
#pragma unroll
                    for (int hf = 0; hf < 2; hf++)
                        mma_bf16(acc[mf][nt * 2 + hf], a[mf], b[nt][hf], b[nt][hf + 2]);
        }
    }
#undef PHYS
#undef ISSUE
}

// ---------------------------------------------------------------------------
// GEMM 1: qkv = g_A1 @ g_W1^T + b_qkv, scatter into Q/K/V [win,h,t,d] fp32
// ---------------------------------------------------------------------------
__global__ void __launch_bounds__(256)
gemm1_kernel(const float* __restrict__ bias) {
    const int m0 = blockIdx.y * 128;
    const int n0 = blockIdx.x * 128;
    float acc[4][4][4];
    gemm_main(g_A1, g_W1, m0, n0, acc);

    const int tid = threadIdx.x;
    const int wid = tid >> 5, lane = tid & 31;
    const int wm = (wid >> 2) * 64, wn = (wid & 3) * 32;
    const int gid = lane >> 2, tig = lane & 3;

#pragma unroll
    for (int mf = 0; mf < 4; mf++) {
#pragma unroll
        for (int q2 = 0; q2 < 2; q2++) {
            const int r = m0 + wm + mf * 16 + gid + q2 * 8;
            const int win = r / NTOK;
            const int t = r - win * NTOK;
#pragma unroll
            for (int nf = 0; nf < 4; nf++) {
#pragma unroll
                for (int j = 0; j < 2; j++) {
                    const int c = n0 + wn + nf * 8 + tig * 2 + j;
                    float v = acc[mf][nf][q2 * 2 + j] + bias[c];
                    const int h = c / 288;
                    const int rm = c - h * 288;
                    const int dd = rm / 3;
                    const int s = rm - dd * 3;
                    const size_t dst = (((size_t)(win * NH + h)) * NTOK + t) * HD + dd;
                    if (s == 0)      g_Q[dst] = v;
                    else if (s == 1) g_K[dst] = v;
                    else             g_V[dst] = v;
                }
            }
        }
    }
}

// ---------------------------------------------------------------------------
// GEMM 3: out = window_reverse(g_Ob @ g_W2^T + b_proj) + x
// ---------------------------------------------------------------------------
__global__ void __launch_bounds__(256)
gemm3_kernel(const float* __restrict__ x,
             const float* __restrict__ bias,
             float* __restrict__ out) {
    const int m0 = blockIdx.y * 128;
    const int n0 = blockIdx.x * 128;
    float acc[4][4][4];
    gemm_main(g_Ob, g_W2, m0, n0, acc);

    const int tid = threadIdx.x;
    const int wid = tid >> 5, lane = tid & 31;
    const int wm = (wid >> 2) * 64, wn = (wid & 3) * 32;
    const int gid = lane >> 2, tig = lane & 3;

#pragma unroll
    for (int mf = 0; mf < 4; mf++) {
#pragma unroll
        for (int q2 = 0; q2 < 2; q2++) {
            const int r = m0 + wm + mf * 16 + gid + q2 * 8;
            const int xr = map_row(r);
#pragma unroll
            for (int nf = 0; nf < 4; nf++) {
#pragma unroll
                for (int j = 0; j < 2; j++) {
                    const int c = n0 + wn + nf * 8 + tig * 2 + j;
                    const size_t idx = (size_t)xr * EMB + c;
                    out[idx] = acc[mf][nf][q2 * 2 + j] + bias[c] + x[idx];
                }
            }
        }
    }
}

// ---------------------------------------------------------------------------
// Attention: one CTA per (win, head). 224 threads, thread t owns query row t.
// Output written bf16 into g_Ob (feeds GEMM3's A operand).
// ---------------------------------------------------------------------------
__global__ void __launch_bounds__(224)
attn_kernel() {
    extern __shared__ float buf[];   // 196*96 floats
    const int wh  = blockIdx.x;
    const int tid = threadIdx.x;
    const size_t base = (size_t)wh * NTOK * HD;

    // stage K
    {
        const float4* src = (const float4*)(g_K + base);
        float4* dst = (float4*)buf;
#pragma unroll
        for (int i = 0; i < 21; i++) dst[tid + i * 224] = src[tid + i * 224];
    }
    __syncthreads();

    const int t = tid;
    float p[NTOK];
    float m = -1e30f, Z = 0.f;

    if (t < NTOK) {
        float4 q[24];
        const float4* qp = (const float4*)(g_Q + base + (size_t)t * HD);
#pragma unroll
        for (int i = 0; i < 24; i++) q[i] = qp[i];

#pragma unroll 1
        for (int k = 0; k < NTOK; k++) {
            const float4* kk = (const float4*)(buf + k * HD);
            float s = 0.f;
#pragma unroll
            for (int i = 0; i < 24; i++) {
                float4 kv = kk[i];
                s += q[i].x * kv.x + q[i].y * kv.y + q[i].z * kv.z + q[i].w * kv.w;
            }
            p[k] = s;
            m = fmaxf(m, s);
        }
#pragma unroll 1
        for (int k = 0; k < NTOK; k++) {
            float e = __expf(p[k] - m);
            p[k] = e;
            Z += e;
        }
    }
    __syncthreads();

    // stage V
    {
        const float4* src = (const float4*)(g_V + base);
        float4* dst = (float4*)buf;
#pragma unroll
        for (int i = 0; i < 21; i++) dst[tid + i * 224] = src[tid + i * 224];
    }
    __syncthreads();

    if (t < NTOK) {
        const float inv = 1.0f / (Z * 27.712812921102035f);   // / (Z * sqrt(768))
        float4 o[24];
#pragma unroll
        for (int i = 0; i < 24; i++) o[i] = make_float4(0.f, 0.f, 0.f, 0.f);

#pragma unroll 1
        for (int k = 0; k < NTOK; k++) {
            const float w = p[k] * inv;
            const float4* vv = (const float4*)(buf + k * HD);
#pragma unroll
            for (int i = 0; i < 24; i++) {
                float4 v = vv[i];
                o[i].x += w * v.x;
                o[i].y += w * v.y;
                o[i].z += w * v.z;
                o[i].w += w * v.w;
            }
        }
        const int win = wh >> 3;
        const int h   = wh & 7;
        uint32_t* op = (uint32_t*)(g_Ob + ((size_t)(win * NTOK + t)) * EMB + h * HD);
#pragma unroll
        for (int i = 0; i < 24; i++) {
            op[i * 2 + 0] = pk(o[i].x, o[i].y);
            op[i * 2 + 1] = pk(o[i].z, o[i].w);
        }
    }
}

// ---------------------------------------------------------------------------
extern "C" void kernel_launch(void* const* d_in, const int* in_sizes, int n_in,
                              void* d_out, int out_size) {
    const float* x      = (const float*)d_in[0];
    const float* w_qkv  = (const float*)d_in[1];
    const float* b_qkv  = (const float*)d_in[2];
    const float* w_proj = (const float*)d_in[3];
    const float* b_proj = (const float*)d_in[4];
    float* out = (float*)d_out;

    conv_x_kernel<<<MROWS * 96 / 256, 256>>>(x);
    conv_w1_kernel<<<QKVC * 96 / 256, 256>>>(w_qkv);
    conv_w2_kernel<<<EMB * 96 / 256, 256>>>(w_proj);

    dim3 g1(QKVC / 128, MROWS / 128);
    gemm1_kernel<<<g1, 256>>>(b_qkv);

    const int smem = NTOK * HD * sizeof(float);
    cudaFuncSetAttribute(attn_kernel, cudaFuncAttributeMaxDynamicSharedMemorySize, smem);
    attn_kernel<<<NWIN * NH, 224, smem>>>();

    dim3 g3(EMB / 128, MROWS / 128);
    gemm3_kernel<<<g3, 256>>>(x, b_proj, out);
}

// round 4
// speedup vs baseline: 4.5582x; 1.8579x over previous
#include <cuda_runtime.h>
#include <cuda_bf16.h>
#include <cstdint>

// ---------------------------------------------------------------------------
// WindowedMultiHeadAttention — bf16 mma.sync everywhere.
// ---------------------------------------------------------------------------

#define EMB   768
#define NH    8
#define HD    96
#define NWIN  256
#define NTOK  196
#define MROWS (NWIN * NTOK)   // 50176
#define QKVC  (3 * EMB)       // 2304

// scratch (device globals: allocation-free)
__device__ __nv_bfloat16 g_Qb[NWIN * NH * NTOK * HD];
__device__ __nv_bfloat16 g_Kb[NWIN * NH * NTOK * HD];
__device__ __nv_bfloat16 g_Vb[NWIN * NH * NTOK * HD];
__device__ __nv_bfloat16 g_A1[MROWS * EMB];   // window-gathered x, bf16
__device__ __nv_bfloat16 g_W1[QKVC * EMB];    // w_qkv transposed [c][k], bf16
__device__ __nv_bfloat16 g_W2[EMB * EMB];     // w_proj transposed [c][k], bf16
__device__ __nv_bfloat16 g_Ob[MROWS * EMB];   // attention output, bf16

// map window-space row (win*196 + t) -> row index in x (B,3136,C)
__device__ __forceinline__ int map_row(int r) {
    int win = r / NTOK;
    int t   = r - win * NTOK;
    int b   = win >> 4;
    int wr  = win & 15;
    int wh  = wr >> 2;
    int ww  = wr & 3;
    int i   = t / 14;
    int j   = t - i * 14;
    return (b * 56 + wh * 14 + i) * 56 + (ww * 14 + j);
}

__device__ __forceinline__ uint32_t pk(float x, float y) {
    __nv_bfloat162 h = __floats2bfloat162_rn(x, y);
    return *reinterpret_cast<uint32_t*>(&h);
}

__device__ __forceinline__ void cp16(uint32_t dst, const void* src) {
    asm volatile("cp.async.cg.shared.global [%0], [%1], 16;" :: "r"(dst), "l"(src));
}
__device__ __forceinline__ void cp_commit() {
    asm volatile("cp.async.commit_group;");
}

__device__ __forceinline__ void ldsm4(uint32_t* r, uint32_t addr) {
    asm volatile("ldmatrix.sync.aligned.m8n8.x4.shared.b16 {%0,%1,%2,%3}, [%4];"
                 : "=r"(r[0]), "=r"(r[1]), "=r"(r[2]), "=r"(r[3]) : "r"(addr));
}
__device__ __forceinline__ void ldsm4t(uint32_t* r, uint32_t addr) {
    asm volatile("ldmatrix.sync.aligned.m8n8.x4.trans.shared.b16 {%0,%1,%2,%3}, [%4];"
                 : "=r"(r[0]), "=r"(r[1]), "=r"(r[2]), "=r"(r[3]) : "r"(addr));
}

__device__ __forceinline__ void mma_bf16(float* d, const uint32_t* a, uint32_t b0, uint32_t b1) {
    asm volatile(
        "mma.sync.aligned.m16n8k16.row.col.f32.bf16.bf16.f32 "
        "{%0,%1,%2,%3}, {%4,%5,%6,%7}, {%8,%9}, {%0,%1,%2,%3};"
        : "+f"(d[0]), "+f"(d[1]), "+f"(d[2]), "+f"(d[3])
        : "r"(a[0]), "r"(a[1]), "r"(a[2]), "r"(a[3]), "r"(b0), "r"(b1));
}

// ---------------------------------------------------------------------------
// prep kernels
// ---------------------------------------------------------------------------
__global__ void conv_x_kernel(const float* __restrict__ x) {
    int g  = blockIdx.x * 256 + threadIdx.x;
    int r  = g / 96;
    int kc = (g - r * 96) * 8;
    const float* s = x + (size_t)map_row(r) * EMB + kc;
    float4 v0 = *(const float4*)s;
    float4 v1 = *(const float4*)(s + 4);
    uint4 u;
    u.x = pk(v0.x, v0.y); u.y = pk(v0.z, v0.w);
    u.z = pk(v1.x, v1.y); u.w = pk(v1.z, v1.w);
    *(uint4*)(g_A1 + (size_t)r * EMB + kc) = u;
}

__global__ void conv_w1_kernel(const float* __restrict__ w) {
    int g  = blockIdx.x * 256 + threadIdx.x;
    int c  = g / 96;
    int k0 = (g - c * 96) * 8;
    float v[8];
#pragma unroll
    for (int i = 0; i < 8; i++) v[i] = w[(size_t)(k0 + i) * QKVC + c];
    uint4 u;
    u.x = pk(v[0], v[1]); u.y = pk(v[2], v[3]);
    u.z = pk(v[4], v[5]); u.w = pk(v[6], v[7]);
    *(uint4*)(g_W1 + (size_t)c * EMB + k0) = u;
}

__global__ void conv_w2_kernel(const float* __restrict__ w) {
    int g  = blockIdx.x * 256 + threadIdx.x;
    int c  = g / 96;
    int k0 = (g - c * 96) * 8;
    float v[8];
#pragma unroll
    for (int i = 0; i < 8; i++) v[i] = w[(size_t)(k0 + i) * EMB + c];
    uint4 u;
    u.x = pk(v[0], v[1]); u.y = pk(v[2], v[3]);
    u.z = pk(v[4], v[5]); u.w = pk(v[6], v[7]);
    *(uint4*)(g_W2 + (size_t)c * EMB + k0) = u;
}

// ---------------------------------------------------------------------------
// Shared bf16 GEMM mainloop (same as R3): C[128x128] = A @ B^T, K=768
// ---------------------------------------------------------------------------
__device__ __forceinline__ void gemm_main(const __nv_bfloat16* __restrict__ Asrc,
                                          const __nv_bfloat16* __restrict__ Bsrc,
                                          int m0, int n0,
                                          float (&acc)[4][4][4]) {
    __shared__ uint4 smem[3 * 1024];
    const int tid = threadIdx.x;
    const uint32_t sbase = (uint32_t)__cvta_generic_to_shared(smem);

#pragma unroll
    for (int i = 0; i < 4; i++)
#pragma unroll
        for (int j = 0; j < 4; j++)
#pragma unroll
            for (int q = 0; q < 4; q++) acc[i][j][q] = 0.f;

    const int srow = tid >> 1;
    const int skc0 = (tid & 1) * 2;

    const int wid = tid >> 5, lane = tid & 31;
    const int wm = (wid >> 2) * 64, wn = (wid & 3) * 32;
    const int lr = lane & 15, khalf = lane >> 4;

#define PHYS(stage, half, row, kc) \
    (sbase + (uint32_t)(((stage) * 1024 + (half) * 512 + (row) * 4 + ((kc) ^ (((row) >> 1) & 3))) * 16))

#define ISSUE(stage, k0)                                                           \
    do {                                                                           \
        _Pragma("unroll")                                                          \
        for (int i = 0; i < 2; i++) {                                              \
            int kc = skc0 + i;                                                     \
            cp16(PHYS(stage, 0, srow, kc), Asrc + (size_t)(m0 + srow) * EMB + (k0) + kc * 8); \
            cp16(PHYS(stage, 1, srow, kc), Bsrc + (size_t)(n0 + srow) * EMB + (k0) + kc * 8); \
        }                                                                          \
    } while (0)

    ISSUE(0, 0); cp_commit();
    ISSUE(1, 32); cp_commit();

#pragma unroll 1
    for (int it = 0; it < 24; it++) {
        asm volatile("cp.async.wait_group 1;");
        __syncthreads();
        if (it + 2 < 24) {
            int ns = (it + 2) % 3;
            ISSUE(ns, (it + 2) * 32);
        }
        cp_commit();
        const int st = it % 3;
#pragma unroll
        for (int kki = 0; kki < 2; kki++) {
            uint32_t a[4][4], b[2][4];
            const int kc = kki * 2 + khalf;
#pragma unroll
            for (int mf = 0; mf < 4; mf++)
                ldsm4(a[mf], PHYS(st, 0, wm + mf * 16 + lr, kc));
#pragma unroll
            for (int nt = 0; nt < 2; nt++)
                ldsm4(b[nt], PHYS(st, 1, wn + nt * 16 + lr, kc));
#pragma unroll
            for (int mf = 0; mf < 4; mf++)
#pragma unroll
                for (int nt = 0; nt < 2; nt++)
#pragma unroll
                    for (int hf = 0; hf < 2; hf++)
                        mma_bf16(acc[mf][nt * 2 + hf], a[mf], b[nt][hf], b[nt][hf + 2]);
        }
    }
#undef PHYS
#undef ISSUE
}

// ---------------------------------------------------------------------------
// GEMM 1: qkv = g_A1 @ g_W1^T + b_qkv, scatter bf16 into Q/K/V [wh][t][d]
// ---------------------------------------------------------------------------
__global__ void __launch_bounds__(256)
gemm1_kernel(const float* __restrict__ bias) {
    const int m0 = blockIdx.y * 128;
    const int n0 = blockIdx.x * 128;
    float acc[4][4][4];
    gemm_main(g_A1, g_W1, m0, n0, acc);

    const int tid = threadIdx.x;
    const int wid = tid >> 5, lane = tid & 31;
    const int wm = (wid >> 2) * 64, wn = (wid & 3) * 32;
    const int gid = lane >> 2, tig = lane & 3;

#pragma unroll
    for (int mf = 0; mf < 4; mf++) {
#pragma unroll
        for (int q2 = 0; q2 < 2; q2++) {
            const int r = m0 + wm + mf * 16 + gid + q2 * 8;
            const int win = r / NTOK;
            const int t = r - win * NTOK;
#pragma unroll
            for (int nf = 0; nf < 4; nf++) {
#pragma unroll
                for (int j = 0; j < 2; j++) {
                    const int c = n0 + wn + nf * 8 + tig * 2 + j;
                    float v = acc[mf][nf][q2 * 2 + j] + bias[c];
                    const int h = c / 288;
                    const int rm = c - h * 288;
                    const int dd = rm / 3;
                    const int s = rm - dd * 3;
                    const size_t dst = (((size_t)(win * NH + h)) * NTOK + t) * HD + dd;
                    __nv_bfloat16 bv = __float2bfloat16(v);
                    if (s == 0)      g_Qb[dst] = bv;
                    else if (s == 1) g_Kb[dst] = bv;
                    else             g_Vb[dst] = bv;
                }
            }
        }
    }
}

// ---------------------------------------------------------------------------
// GEMM 3: out = window_reverse(g_Ob @ g_W2^T + b_proj) + x
// ---------------------------------------------------------------------------
__global__ void __launch_bounds__(256)
gemm3_kernel(const float* __restrict__ x,
             const float* __restrict__ bias,
             float* __restrict__ out) {
    const int m0 = blockIdx.y * 128;
    const int n0 = blockIdx.x * 128;
    float acc[4][4][4];
    gemm_main(g_Ob, g_W2, m0, n0, acc);

    const int tid = threadIdx.x;
    const int wid = tid >> 5, lane = tid & 31;
    const int wm = (wid >> 2) * 64, wn = (wid & 3) * 32;
    const int gid = lane >> 2, tig = lane & 3;

#pragma unroll
    for (int mf = 0; mf < 4; mf++) {
#pragma unroll
        for (int q2 = 0; q2 < 2; q2++) {
            const int r = m0 + wm + mf * 16 + gid + q2 * 8;
            const int xr = map_row(r);
#pragma unroll
            for (int nf = 0; nf < 4; nf++) {
#pragma unroll
                for (int j = 0; j < 2; j++) {
                    const int c = n0 + wn + nf * 8 + tig * 2 + j;
                    const size_t idx = (size_t)xr * EMB + c;
                    out[idx] = acc[mf][nf][q2 * 2 + j] + bias[c] + x[idx];
                }
            }
        }
    }
}

// ---------------------------------------------------------------------------
// Attention (tensor cores): one CTA per (win,head), 224 thr = 7 warps.
// Warp w owns query rows [32w, 32w+32). M padded to 224, online softmax.
// smem: Q,K,V each [224 rows][104 bf16] (208B stride, conflict-free ldsm).
// ---------------------------------------------------------------------------
#define QSTR 104          // bf16 per smem row (208 bytes)
#define AT_BYTES (224 * QSTR * 2)

__global__ void __launch_bounds__(224, 1)
attn_tc_kernel() {
    extern __shared__ __align__(16) char smem[];
    const int wh  = blockIdx.x;
    const int tid = threadIdx.x;
    const uint32_t sb = (uint32_t)__cvta_generic_to_shared(smem);
    const uint32_t Qo = sb, Ko = sb + AT_BYTES, Vo = sb + 2 * AT_BYTES;

    const __nv_bfloat16* gq = g_Qb + (size_t)wh * NTOK * HD;
    const __nv_bfloat16* gk = g_Kb + (size_t)wh * NTOK * HD;
    const __nv_bfloat16* gv = g_Vb + (size_t)wh * NTOK * HD;

    // stage Q,K,V (196 rows x 12 16B-chunks each)
    for (int i = tid; i < NTOK * 12; i += 224) {
        int t = i / 12, c = i - t * 12;
        uint32_t off = (uint32_t)(t * 208 + c * 16);
        const size_t g = (size_t)t * HD + c * 8;
        cp16(Qo + off, gq + g);
        cp16(Ko + off, gk + g);
        cp16(Vo + off, gv + g);
    }
    cp_commit();
    // zero pad rows 196..223 (13 chunks to cover full 208B rows)
    for (int i = tid; i < 28 * 13; i += 224) {
        int t = 196 + i / 13, c = i - (i / 13) * 13;
        uint32_t off = (uint32_t)(t * 208 + c * 16);
        uint4 z = make_uint4(0, 0, 0, 0);
        *(uint4*)(smem + (Qo - sb) + off) = z;
        *(uint4*)(smem + (Ko - sb) + off) = z;
        *(uint4*)(smem + (Vo - sb) + off) = z;
    }
    asm volatile("cp.async.wait_group 0;");
    __syncthreads();

    const int w = tid >> 5;
    const int lane = tid & 31;
    const int gid = lane >> 2, tig = lane & 3;
    const int m0 = w * 32;

    // hoist Q A-fragments: 2 m16 tiles x 6 k16 chunks
    uint32_t aq[2][6][4];
#pragma unroll
    for (int mt = 0; mt < 2; mt++)
#pragma unroll
        for (int kk = 0; kk < 6; kk++)
            ldsm4(aq[mt][kk],
                  Qo + (uint32_t)((m0 + mt * 16 + (lane & 15)) * 208 + kk * 32 + (lane >> 4) * 16));

    float accO[2][12][4];
#pragma unroll
    for (int mt = 0; mt < 2; mt++)
#pragma unroll
        for (int nt = 0; nt < 12; nt++)
#pragma unroll
            for (int q = 0; q < 4; q++) accO[mt][nt][q] = 0.f;

    float rm[2][2] = {{-1e30f, -1e30f}, {-1e30f, -1e30f}};
    float rl[2][2] = {{0.f, 0.f}, {0.f, 0.f}};

#pragma unroll 1
    for (int ch = 0; ch < 7; ch++) {
        const int n0 = ch * 32;

        // ---- S = Q @ K^T chunk (2 mtiles x 4 ntiles) ----
        float s[2][4][4];
#pragma unroll
        for (int mt = 0; mt < 2; mt++)
#pragma unroll
            for (int nt = 0; nt < 4; nt++)
#pragma unroll
                for (int q = 0; q < 4; q++) s[mt][nt][q] = 0.f;

#pragma unroll
        for (int kk = 0; kk < 6; kk++) {
            uint32_t kb0[4], kb1[4];
            uint32_t kaddr = Ko + (uint32_t)((n0 + (lane & 7) + ((lane >> 4) << 3)) * 208
                                             + (kk * 2 + ((lane >> 3) & 1)) * 16);
            ldsm4(kb0, kaddr);
            ldsm4(kb1, kaddr + 16 * 208);
#pragma unroll
            for (int mt = 0; mt < 2; mt++) {
                mma_bf16(s[mt][0], aq[mt][kk], kb0[0], kb0[1]);
                mma_bf16(s[mt][1], aq[mt][kk], kb0[2], kb0[3]);
                mma_bf16(s[mt][2], aq[mt][kk], kb1[0], kb1[1]);
                mma_bf16(s[mt][3], aq[mt][kk], kb1[2], kb1[3]);
            }
        }

        // mask pad key columns (only last chunk holds cols >= 196)
        if (ch == 6) {
#pragma unroll
            for (int mt = 0; mt < 2; mt++)
#pragma unroll
                for (int nt = 0; nt < 4; nt++)
#pragma unroll
                    for (int q = 0; q < 4; q++) {
                        int col = n0 + nt * 8 + tig * 2 + (q & 1);
                        if (col >= NTOK) s[mt][nt][q] = -1e30f;
                    }
        }

        // ---- online softmax update ----
#pragma unroll
        for (int mt = 0; mt < 2; mt++) {
#pragma unroll
            for (int hf = 0; hf < 2; hf++) {
                float mx = -1e30f;
#pragma unroll
                for (int nt = 0; nt < 4; nt++) {
                    mx = fmaxf(mx, s[mt][nt][hf * 2]);
                    mx = fmaxf(mx, s[mt][nt][hf * 2 + 1]);
                }
                mx = fmaxf(mx, __shfl_xor_sync(0xffffffff, mx, 1));
                mx = fmaxf(mx, __shfl_xor_sync(0xffffffff, mx, 2));
                float mn = fmaxf(rm[mt][hf], mx);
                float sc = __expf(rm[mt][hf] - mn);
                rm[mt][hf] = mn;
                float ls = 0.f;
#pragma unroll
                for (int nt = 0; nt < 4; nt++) {
                    float p0 = __expf(s[mt][nt][hf * 2] - mn);
                    float p1 = __expf(s[mt][nt][hf * 2 + 1] - mn);
                    s[mt][nt][hf * 2] = p0;
                    s[mt][nt][hf * 2 + 1] = p1;
                    ls += p0 + p1;
                }
                ls += __shfl_xor_sync(0xffffffff, ls, 1);
                ls += __shfl_xor_sync(0xffffffff, ls, 2);
                rl[mt][hf] = rl[mt][hf] * sc + ls;
#pragma unroll
                for (int nt = 0; nt < 12; nt++) {
                    accO[mt][nt][hf * 2]     *= sc;
                    accO[mt][nt][hf * 2 + 1] *= sc;
                }
            }
        }

        // ---- O += P @ V ----
#pragma unroll
        for (int kk = 0; kk < 2; kk++) {
            uint32_t ap[2][4];
#pragma unroll
            for (int mt = 0; mt < 2; mt++) {
                ap[mt][0] = pk(s[mt][kk * 2][0], s[mt][kk * 2][1]);
                ap[mt][1] = pk(s[mt][kk * 2][2], s[mt][kk * 2][3]);
                ap[mt][2] = pk(s[mt][kk * 2 + 1][0], s[mt][kk * 2 + 1][1]);
                ap[mt][3] = pk(s[mt][kk * 2 + 1][2], s[mt][kk * 2 + 1][3]);
            }
#pragma unroll
            for (int u = 0; u < 6; u++) {
                uint32_t vb[4];
                ldsm4t(vb, Vo + (uint32_t)((n0 + kk * 16 + (lane & 7) + (((lane >> 3) & 1) << 3)) * 208
                                           + (u * 2 + (lane >> 4)) * 16));
#pragma unroll
                for (int mt = 0; mt < 2; mt++) {
                    mma_bf16(accO[mt][u * 2],     ap[mt], vb[0], vb[1]);
                    mma_bf16(accO[mt][u * 2 + 1], ap[mt], vb[2], vb[3]);
                }
            }
        }
    }

    // ---- epilogue: normalize and write bf16 into g_Ob ----
    const int win = wh >> 3;
    const int h   = wh & 7;
#pragma unroll
    for (int mt = 0; mt < 2; mt++) {
#pragma unroll
        for (int hf = 0; hf < 2; hf++) {
            const int t = m0 + mt * 16 + gid + hf * 8;
            if (t < NTOK) {
                const float inv = 1.0f / (rl[mt][hf] * 27.712812921102035f);
                uint32_t* op = (uint32_t*)(g_Ob + ((size_t)(win * NTOK + t)) * EMB
                                           + h * HD + tig * 2);
#pragma unroll
                for (int nt = 0; nt < 12; nt++) {
                    op[nt * 4] = pk(accO[mt][nt][hf * 2] * inv,
                                    accO[mt][nt][hf * 2 + 1] * inv);
                }
            }
        }
    }
}

// ---------------------------------------------------------------------------
extern "C" void kernel_launch(void* const* d_in, const int* in_sizes, int n_in,
                              void* d_out, int out_size) {
    const float* x      = (const float*)d_in[0];
    const float* w_qkv  = (const float*)d_in[1];
    const float* b_qkv  = (const float*)d_in[2];
    const float* w_proj = (const float*)d_in[3];
    const float* b_proj = (const float*)d_in[4];
    float* out = (float*)d_out;

    conv_x_kernel<<<MROWS * 96 / 256, 256>>>(x);
    conv_w1_kernel<<<QKVC * 96 / 256, 256>>>(w_qkv);
    conv_w2_kernel<<<EMB * 96 / 256, 256>>>(w_proj);

    dim3 g1(QKVC / 128, MROWS / 128);
    gemm1_kernel<<<g1, 256>>>(b_qkv);

    const int smem = 3 * AT_BYTES;   // 139776
    cudaFuncSetAttribute(attn_tc_kernel, cudaFuncAttributeMaxDynamicSharedMemorySize, smem);
    attn_tc_kernel<<<NWIN * NH, 224, smem>>>();

    dim3 g3(EMB / 128, MROWS / 128);
    gemm3_kernel<<<g3, 256>>>(x, b_proj, out);
}

// round 6
// speedup vs baseline: 7.1511x; 1.5689x over previous
#include <cuda_runtime.h>
#include <cuda_bf16.h>
#include <cstdint>

// ---------------------------------------------------------------------------
// WindowedMultiHeadAttention — bf16 mma.sync everywhere; 64x64 warp tiles.
// ---------------------------------------------------------------------------

#define EMB   768
#define NH    8
#define HD    96
#define NWIN  256
#define NTOK  196
#define MROWS (NWIN * NTOK)   // 50176
#define QKVC  (3 * EMB)       // 2304

// scratch (device globals: allocation-free)
__device__ __align__(16) __nv_bfloat16 g_Qb[NWIN * NH * NTOK * HD];
__device__ __align__(16) __nv_bfloat16 g_Kb[NWIN * NH * NTOK * HD];
__device__ __align__(16) __nv_bfloat16 g_Vb[NWIN * NH * NTOK * HD];
__device__ __align__(16) __nv_bfloat16 g_A1[MROWS * EMB];   // window-gathered x
__device__ __align__(16) __nv_bfloat16 g_W1[QKVC * EMB];    // w_qkv, cols permuted [s][h][dd], K-major
__device__ __align__(16) __nv_bfloat16 g_W2[EMB * EMB];     // w_proj transposed [c][k]
__device__ __align__(16) __nv_bfloat16 g_Ob[MROWS * EMB];   // attention output
__device__ float g_b1p[QKVC];                               // permuted qkv bias

// map window-space row (win*196 + t) -> row index in x (B,3136,C)
__device__ __forceinline__ int map_row(int r) {
    int win = r / NTOK;
    int t   = r - win * NTOK;
    int b   = win >> 4;
    int wr  = win & 15;
    int wh  = wr >> 2;
    int ww  = wr & 3;
    int i   = t / 14;
    int j   = t - i * 14;
    return (b * 56 + wh * 14 + i) * 56 + (ww * 14 + j);
}

__device__ __forceinline__ uint32_t pk(float x, float y) {
    __nv_bfloat162 h = __floats2bfloat162_rn(x, y);
    return *reinterpret_cast<uint32_t*>(&h);
}

__device__ __forceinline__ void cp16(uint32_t dst, const void* src) {
    asm volatile("cp.async.cg.shared.global [%0], [%1], 16;" :: "r"(dst), "l"(src));
}
__device__ __forceinline__ void cp_commit() {
    asm volatile("cp.async.commit_group;");
}

__device__ __forceinline__ void ldsm4(uint32_t* r, uint32_t addr) {
    asm volatile("ldmatrix.sync.aligned.m8n8.x4.shared.b16 {%0,%1,%2,%3}, [%4];"
                 : "=r"(r[0]), "=r"(r[1]), "=r"(r[2]), "=r"(r[3]) : "r"(addr));
}
__device__ __forceinline__ void ldsm4t(uint32_t* r, uint32_t addr) {
    asm volatile("ldmatrix.sync.aligned.m8n8.x4.trans.shared.b16 {%0,%1,%2,%3}, [%4];"
                 : "=r"(r[0]), "=r"(r[1]), "=r"(r[2]), "=r"(r[3]) : "r"(addr));
}

__device__ __forceinline__ void mma_bf16(float* d, const uint32_t* a, uint32_t b0, uint32_t b1) {
    asm volatile(
        "mma.sync.aligned.m16n8k16.row.col.f32.bf16.bf16.f32 "
        "{%0,%1,%2,%3}, {%4,%5,%6,%7}, {%8,%9}, {%0,%1,%2,%3};"
        : "+f"(d[0]), "+f"(d[1]), "+f"(d[2]), "+f"(d[3])
        : "r"(a[0]), "r"(a[1]), "r"(a[2]), "r"(a[3]), "r"(b0), "r"(b1));
}

// ---------------------------------------------------------------------------
// prep kernels
// ---------------------------------------------------------------------------
__global__ void conv_x_kernel(const float* __restrict__ x) {
    int g  = blockIdx.x * 256 + threadIdx.x;
    int r  = g / 96;
    int kc = (g - r * 96) * 8;
    const float* s = x + (size_t)map_row(r) * EMB + kc;
    float4 v0 = *(const float4*)s;
    float4 v1 = *(const float4*)(s + 4);
    uint4 u;
    u.x = pk(v0.x, v0.y); u.y = pk(v0.z, v0.w);
    u.z = pk(v1.x, v1.y); u.w = pk(v1.z, v1.w);
    *(uint4*)(g_A1 + (size_t)r * EMB + kc) = u;
}

// w_qkv: old col c = h*288 + dd*3 + s  ->  new col c' = s*768 + h*96 + dd
__global__ void conv_w1_kernel(const float* __restrict__ w) {
    int g  = blockIdx.x * 256 + threadIdx.x;     // QKVC*96 threads
    int c  = g / 96;
    int k0 = (g - c * 96) * 8;
    int h  = c / 288;
    int rm = c - h * 288;
    int dd = rm / 3;
    int s  = rm - dd * 3;
    int cp_ = s * 768 + h * 96 + dd;
    float v[8];
#pragma unroll
    for (int i = 0; i < 8; i++) v[i] = w[(size_t)(k0 + i) * QKVC + c];
    uint4 u;
    u.x = pk(v[0], v[1]); u.y = pk(v[2], v[3]);
    u.z = pk(v[4], v[5]); u.w = pk(v[6], v[7]);
    *(uint4*)(g_W1 + (size_t)cp_ * EMB + k0) = u;
}

__global__ void conv_b1_kernel(const float* __restrict__ b) {
    int c = blockIdx.x * 256 + threadIdx.x;      // 2304
    int h  = c / 288;
    int rm = c - h * 288;
    int dd = rm / 3;
    int s  = rm - dd * 3;
    g_b1p[s * 768 + h * 96 + dd] = b[c];
}

__global__ void conv_w2_kernel(const float* __restrict__ w) {
    int g  = blockIdx.x * 256 + threadIdx.x;
    int c  = g / 96;
    int k0 = (g - c * 96) * 8;
    float v[8];
#pragma unroll
    for (int i = 0; i < 8; i++) v[i] = w[(size_t)(k0 + i) * EMB + c];
    uint4 u;
    u.x = pk(v[0], v[1]); u.y = pk(v[2], v[3]);
    u.z = pk(v[4], v[5]); u.w = pk(v[6], v[7]);
    *(uint4*)(g_W2 + (size_t)c * EMB + k0) = u;
}

// ---------------------------------------------------------------------------
// bf16 GEMM mainloop: C[128m x 256n] = A[128 rows,K=768] @ B[256 rows,K]^T
// 256 threads, 8 warps of 64x64 (2x4). BK=64, 3-stage cp.async.
// stage layout: A 128 rows x 128B (16KB), B 256 rows x 128B (32KB) = 48KB.
// phys(row, c16) = row*128 + ((c16 ^ (row&7)) << 4)   (SW128 pattern)
// ---------------------------------------------------------------------------
#define STG 49152
#define GSMEM (3 * STG)

__device__ __forceinline__ void g_fill(uint32_t sb, int stage,
                                       const __nv_bfloat16* __restrict__ A,
                                       const __nv_bfloat16* __restrict__ B,
                                       int m0, int n0, int kc, int tid) {
    uint32_t abase = sb + stage * STG;
    uint32_t bbase = abase + 16384;
#pragma unroll
    for (int i = 0; i < 4; i++) {
        int idx = tid + i * 256;             // 0..1023
        int r = idx >> 3, c = idx & 7;
        uint32_t sw = (uint32_t)(r * 128 + ((c ^ (r & 7)) << 4));
        cp16(abase + sw, A + (size_t)(m0 + r) * EMB + kc + c * 8);
    }
#pragma unroll
    for (int i = 0; i < 8; i++) {
        int idx = tid + i * 256;             // 0..2047
        int r = idx >> 3, c = idx & 7;
        uint32_t sw = (uint32_t)(r * 128 + ((c ^ (r & 7)) << 4));
        cp16(bbase + sw, B + (size_t)(n0 + r) * EMB + kc + c * 8);
    }
}

__device__ __forceinline__ void gemm_main(const __nv_bfloat16* __restrict__ A,
                                          const __nv_bfloat16* __restrict__ B,
                                          int m0, int n0,
                                          float (&acc)[4][8][4]) {
    extern __shared__ __align__(16) char dsm[];
    const uint32_t sb = (uint32_t)__cvta_generic_to_shared(dsm);
    const int tid = threadIdx.x;

#pragma unroll
    for (int i = 0; i < 4; i++)
#pragma unroll
        for (int j = 0; j < 8; j++)
#pragma unroll
            for (int q = 0; q < 4; q++) acc[i][j][q] = 0.f;

    const int wid = tid >> 5, lane = tid & 31;
    const int wm = (wid >> 2) * 64;          // 0 / 64
    const int wn = (wid & 3) * 64;           // 0 / 64 / 128 / 192
    const int lr = lane & 15, khalf = lane >> 4;

    g_fill(sb, 0, A, B, m0, n0, 0, tid);   cp_commit();
    g_fill(sb, 1, A, B, m0, n0, 64, tid);  cp_commit();
    g_fill(sb, 2, A, B, m0, n0, 128, tid); cp_commit();

#pragma unroll 1
    for (int it = 0; it < 12; it++) {
        asm volatile("cp.async.wait_group 2;");
        __syncthreads();
        const int st = it % 3;
        const uint32_t abase = sb + st * STG;
        const uint32_t bbase = abase + 16384;
#pragma unroll
        for (int kk = 0; kk < 4; kk++) {
            uint32_t a[4][4], b[4][4];
            const int kc = kk * 2 + khalf;
#pragma unroll
            for (int mf = 0; mf < 4; mf++) {
                int r = wm + mf * 16 + lr;
                ldsm4(a[mf], abase + (uint32_t)(r * 128 + ((kc ^ (r & 7)) << 4)));
            }
#pragma unroll
            for (int nt = 0; nt < 4; nt++) {
                int r = wn + nt * 16 + lr;
                ldsm4(b[nt], bbase + (uint32_t)(r * 128 + ((kc ^ (r & 7)) << 4)));
            }
#pragma unroll
            for (int mf = 0; mf < 4; mf++)
#pragma unroll
                for (int nt = 0; nt < 4; nt++) {
                    mma_bf16(acc[mf][nt * 2],     a[mf], b[nt][0], b[nt][2]);
                    mma_bf16(acc[mf][nt * 2 + 1], a[mf], b[nt][1], b[nt][3]);
                }
        }
        __syncthreads();
        if (it + 3 < 12) g_fill(sb, st, A, B, m0, n0, (it + 3) * 64, tid);
        cp_commit();
    }
}

// ---------------------------------------------------------------------------
// GEMM 1: qkv = g_A1 @ g_W1^T + b1p -> bf16 Q/K/V [wh][t][d]
// grid (9, 392)
// ---------------------------------------------------------------------------
__global__ void __launch_bounds__(256, 1)
gemm1_kernel() {
    const int m0 = blockIdx.y * 128;
    const int n0 = blockIdx.x * 256;
    float acc[4][8][4];
    gemm_main(g_A1, g_W1, m0, n0, acc);

    const int tid = threadIdx.x, wid = tid >> 5, lane = tid & 31;
    const int wm = (wid >> 2) * 64, wn = (wid & 3) * 64;
    const int gid = lane >> 2, tig = lane & 3;

#pragma unroll
    for (int mf = 0; mf < 4; mf++) {
#pragma unroll
        for (int q2 = 0; q2 < 2; q2++) {
            const int r = m0 + wm + mf * 16 + gid + q2 * 8;
            const int win = r / NTOK;
            const int t = r - win * NTOK;
#pragma unroll
            for (int nf = 0; nf < 8; nf++) {
                const int c = n0 + wn + nf * 8 + tig * 2;
                const int s  = c / 768;
                const int rm = c - s * 768;
                const int h  = rm / 96;
                const int dd = rm - h * 96;
                float v0 = acc[mf][nf][q2 * 2]     + g_b1p[c];
                float v1 = acc[mf][nf][q2 * 2 + 1] + g_b1p[c + 1];
                __nv_bfloat16* base = (s == 0 ? g_Qb : (s == 1 ? g_Kb : g_Vb))
                                      + ((size_t)(win * NH + h) * NTOK + t) * HD + dd;
                *(uint32_t*)base = pk(v0, v1);
            }
        }
    }
}

// ---------------------------------------------------------------------------
// GEMM 3: out = window_reverse(g_Ob @ g_W2^T + b_proj) + x
// grid (3, 392)
// ---------------------------------------------------------------------------
__global__ void __launch_bounds__(256, 1)
gemm3_kernel(const float* __restrict__ x,
             const float* __restrict__ bias,
             float* __restrict__ out) {
    const int m0 = blockIdx.y * 128;
    const int n0 = blockIdx.x * 256;
    float acc[4][8][4];
    gemm_main(g_Ob, g_W2, m0, n0, acc);

    const int tid = threadIdx.x, wid = tid >> 5, lane = tid & 31;
    const int wm = (wid >> 2) * 64, wn = (wid & 3) * 64;
    const int gid = lane >> 2, tig = lane & 3;

#pragma unroll
    for (int mf = 0; mf < 4; mf++) {
#pragma unroll
        for (int q2 = 0; q2 < 2; q2++) {
            const int r = m0 + wm + mf * 16 + gid + q2 * 8;
            const int xr = map_row(r);
#pragma unroll
            for (int nf = 0; nf < 8; nf++) {
                const int c = n0 + wn + nf * 8 + tig * 2;
                const size_t idx = (size_t)xr * EMB + c;
                float2 xv = *(const float2*)(x + idx);
                out[idx]     = acc[mf][nf][q2 * 2]     + bias[c]     + xv.x;
                out[idx + 1] = acc[mf][nf][q2 * 2 + 1] + bias[c + 1] + xv.y;
            }
        }
    }
}

// ---------------------------------------------------------------------------
// Attention (mma.sync, unchanged from R4): one CTA per (win,head), 224 thr.
// ---------------------------------------------------------------------------
#define QSTR 104
#define AT_BYTES (224 * QSTR * 2)

__global__ void __launch_bounds__(224, 1)
attn_tc_kernel() {
    extern __shared__ __align__(16) char smem[];
    const int wh  = blockIdx.x;
    const int tid = threadIdx.x;
    const uint32_t sb = (uint32_t)__cvta_generic_to_shared(smem);
    const uint32_t Qo = sb, Ko = sb + AT_BYTES, Vo = sb + 2 * AT_BYTES;

    const __nv_bfloat16* gq = g_Qb + (size_t)wh * NTOK * HD;
    const __nv_bfloat16* gk = g_Kb + (size_t)wh * NTOK * HD;
    const __nv_bfloat16* gv = g_Vb + (size_t)wh * NTOK * HD;

    for (int i = tid; i < NTOK * 12; i += 224) {
        int t = i / 12, c = i - t * 12;
        uint32_t off = (uint32_t)(t * 208 + c * 16);
        const size_t g = (size_t)t * HD + c * 8;
        cp16(Qo + off, gq + g);
        cp16(Ko + off, gk + g);
        cp16(Vo + off, gv + g);
    }
    cp_commit();
    for (int i = tid; i < 28 * 13; i += 224) {
        int t = 196 + i / 13, c = i - (i / 13) * 13;
        uint32_t off = (uint32_t)(t * 208 + c * 16);
        uint4 z = make_uint4(0, 0, 0, 0);
        *(uint4*)(smem + (Qo - sb) + off) = z;
        *(uint4*)(smem + (Ko - sb) + off) = z;
        *(uint4*)(smem + (Vo - sb) + off) = z;
    }
    asm volatile("cp.async.wait_group 0;");
    __syncthreads();

    const int w = tid >> 5;
    const int lane = tid & 31;
    const int gid = lane >> 2, tig = lane & 3;
    const int m0 = w * 32;

    uint32_t aq[2][6][4];
#pragma unroll
    for (int mt = 0; mt < 2; mt++)
#pragma unroll
        for (int kk = 0; kk < 6; kk++)
            ldsm4(aq[mt][kk],
                  Qo + (uint32_t)((m0 + mt * 16 + (lane & 15)) * 208 + kk * 32 + (lane >> 4) * 16));

    float accO[2][12][4];
#pragma unroll
    for (int mt = 0; mt < 2; mt++)
#pragma unroll
        for (int nt = 0; nt < 12; nt++)
#pragma unroll
            for (int q = 0; q < 4; q++) accO[mt][nt][q] = 0.f;

    float rm[2][2] = {{-1e30f, -1e30f}, {-1e30f, -1e30f}};
    float rl[2][2] = {{0.f, 0.f}, {0.f, 0.f}};

#pragma unroll 1
    for (int ch = 0; ch < 7; ch++) {
        const int n0 = ch * 32;
        float s[2][4][4];
#pragma unroll
        for (int mt = 0; mt < 2; mt++)
#pragma unroll
            for (int nt = 0; nt < 4; nt++)
#pragma unroll
                for (int q = 0; q < 4; q++) s[mt][nt][q] = 0.f;

#pragma unroll
        for (int kk = 0; kk < 6; kk++) {
            uint32_t kb0[4], kb1[4];
            uint32_t kaddr = Ko + (uint32_t)((n0 + (lane & 7) + ((lane >> 4) << 3)) * 208
                                             + (kk * 2 + ((lane >> 3) & 1)) * 16);
            ldsm4(kb0, kaddr);
            ldsm4(kb1, kaddr + 16 * 208);
#pragma unroll
            for (int mt = 0; mt < 2; mt++) {
                mma_bf16(s[mt][0], aq[mt][kk], kb0[0], kb0[1]);
                mma_bf16(s[mt][1], aq[mt][kk], kb0[2], kb0[3]);
                mma_bf16(s[mt][2], aq[mt][kk], kb1[0], kb1[1]);
                mma_bf16(s[mt][3], aq[mt][kk], kb1[2], kb1[3]);
            }
        }

        if (ch == 6) {
#pragma unroll
            for (int mt = 0; mt < 2; mt++)
#pragma unroll
                for (int nt = 0; nt < 4; nt++)
#pragma unroll
                    for (int q = 0; q < 4; q++) {
                        int col = n0 + nt * 8 + tig * 2 + (q & 1);
                        if (col >= NTOK) s[mt][nt][q] = -1e30f;
                    }
        }

#pragma unroll
        for (int mt = 0; mt < 2; mt++) {
#pragma unroll
            for (int hf = 0; hf < 2; hf++) {
                float mx = -1e30f;
#pragma unroll
                for (int nt = 0; nt < 4; nt++) {
                    mx = fmaxf(mx, s[mt][nt][hf * 2]);
                    mx = fmaxf(mx, s[mt][nt][hf * 2 + 1]);
                }
                mx = fmaxf(mx, __shfl_xor_sync(0xffffffff, mx, 1));
                mx = fmaxf(mx, __shfl_xor_sync(0xffffffff, mx, 2));
                float mn = fmaxf(rm[mt][hf], mx);
                float sc = __expf(rm[mt][hf] - mn);
                rm[mt][hf] = mn;
                float ls = 0.f;
#pragma unroll
                for (int nt = 0; nt < 4; nt++) {
                    float p0 = __expf(s[mt][nt][hf * 2] - mn);
                    float p1 = __expf(s[mt][nt][hf * 2 + 1] - mn);
                    s[mt][nt][hf * 2] = p0;
                    s[mt][nt][hf * 2 + 1] = p1;
                    ls += p0 + p1;
                }
                ls += __shfl_xor_sync(0xffffffff, ls, 1);
                ls += __shfl_xor_sync(0xffffffff, ls, 2);
                rl[mt][hf] = rl[mt][hf] * sc + ls;
#pragma unroll
                for (int nt = 0; nt < 12; nt++) {
                    accO[mt][nt][hf * 2]     *= sc;
                    accO[mt][nt][hf * 2 + 1] *= sc;
                }
            }
        }

#pragma unroll
        for (int kk = 0; kk < 2; kk++) {
            uint32_t ap[2][4];
#pragma unroll
            for (int mt = 0; mt < 2; mt++) {
                ap[mt][0] = pk(s[mt][kk * 2][0], s[mt][kk * 2][1]);
                ap[mt][1] = pk(s[mt][kk * 2][2], s[mt][kk * 2][3]);
                ap[mt][2] = pk(s[mt][kk * 2 + 1][0], s[mt][kk * 2 + 1][1]);
                ap[mt][3] = pk(s[mt][kk * 2 + 1][2], s[mt][kk * 2 + 1][3]);
            }
#pragma unroll
            for (int u = 0; u < 6; u++) {
                uint32_t vb[4];
                ldsm4t(vb, Vo + (uint32_t)((n0 + kk * 16 + (lane & 7) + (((lane >> 3) & 1) << 3)) * 208
                                           + (u * 2 + (lane >> 4)) * 16));
#pragma unroll
                for (int mt = 0; mt < 2; mt++) {
                    mma_bf16(accO[mt][u * 2],     ap[mt], vb[0], vb[1]);
                    mma_bf16(accO[mt][u * 2 + 1], ap[mt], vb[2], vb[3]);
                }
            }
        }
    }

    const int win = wh >> 3;
    const int h   = wh & 7;
#pragma unroll
    for (int mt = 0; mt < 2; mt++) {
#pragma unroll
        for (int hf = 0; hf < 2; hf++) {
            const int t = m0 + mt * 16 + gid + hf * 8;
            if (t < NTOK) {
                const float inv = 1.0f / (rl[mt][hf] * 27.712812921102035f);
                uint32_t* op = (uint32_t*)(g_Ob + ((size_t)(win * NTOK + t)) * EMB
                                           + h * HD + tig * 2);
#pragma unroll
                for (int nt = 0; nt < 12; nt++) {
                    op[nt * 4] = pk(accO[mt][nt][hf * 2] * inv,
                                    accO[mt][nt][hf * 2 + 1] * inv);
                }
            }
        }
    }
}

// ---------------------------------------------------------------------------
extern "C" void kernel_launch(void* const* d_in, const int* in_sizes, int n_in,
                              void* d_out, int out_size) {
    const float* x      = (const float*)d_in[0];
    const float* w_qkv  = (const float*)d_in[1];
    const float* b_qkv  = (const float*)d_in[2];
    const float* w_proj = (const float*)d_in[3];
    const float* b_proj = (const float*)d_in[4];
    float* out = (float*)d_out;

    conv_x_kernel<<<MROWS * 96 / 256, 256>>>(x);
    conv_w1_kernel<<<QKVC * 96 / 256, 256>>>(w_qkv);
    conv_b1_kernel<<<QKVC / 256, 256>>>(b_qkv);
    conv_w2_kernel<<<EMB * 96 / 256, 256>>>(w_proj);

    cudaFuncSetAttribute(gemm1_kernel, cudaFuncAttributeMaxDynamicSharedMemorySize, GSMEM);
    gemm1_kernel<<<dim3(QKVC / 256, MROWS / 128), 256, GSMEM>>>();

    const int asmem = 3 * AT_BYTES;
    cudaFuncSetAttribute(attn_tc_kernel, cudaFuncAttributeMaxDynamicSharedMemorySize, asmem);
    attn_tc_kernel<<<NWIN * NH, 224, asmem>>>();

    cudaFuncSetAttribute(gemm3_kernel, cudaFuncAttributeMaxDynamicSharedMemorySize, GSMEM);
    gemm3_kernel<<<dim3(EMB / 256, MROWS / 128), 256, GSMEM>>>(x, b_proj, out);
}

// round 7
// speedup vs baseline: 7.3739x; 1.0312x over previous
#include <cuda_runtime.h>
#include <cuda_bf16.h>
#include <cstdint>

// ---------------------------------------------------------------------------
// WindowedMultiHeadAttention — bf16 mma.sync; 4-stage GEMM pipeline;
// query-split attention (2 CTAs per (win,head), 2 CTAs/SM).
// ---------------------------------------------------------------------------

#define EMB   768
#define NH    8
#define HD    96
#define NWIN  256
#define NTOK  196
#define MROWS (NWIN * NTOK)   // 50176
#define QKVC  (3 * EMB)       // 2304

// scratch (device globals: allocation-free)
__device__ __align__(16) __nv_bfloat16 g_Qb[NWIN * NH * NTOK * HD];
__device__ __align__(16) __nv_bfloat16 g_Kb[NWIN * NH * NTOK * HD];
__device__ __align__(16) __nv_bfloat16 g_Vb[NWIN * NH * NTOK * HD];
__device__ __align__(16) __nv_bfloat16 g_A1[MROWS * EMB];   // window-gathered x
__device__ __align__(16) __nv_bfloat16 g_W1[QKVC * EMB];    // w_qkv permuted [s][h][dd], K-major
__device__ __align__(16) __nv_bfloat16 g_W2[EMB * EMB];     // w_proj transposed [c][k]
__device__ __align__(16) __nv_bfloat16 g_Ob[MROWS * EMB];   // attention output
__device__ float g_b1p[QKVC];                               // permuted qkv bias

// map window-space row (win*196 + t) -> row index in x (B,3136,C)
__device__ __forceinline__ int map_row(int r) {
    int win = r / NTOK;
    int t   = r - win * NTOK;
    int b   = win >> 4;
    int wr  = win & 15;
    int wh  = wr >> 2;
    int ww  = wr & 3;
    int i   = t / 14;
    int j   = t - i * 14;
    return (b * 56 + wh * 14 + i) * 56 + (ww * 14 + j);
}

__device__ __forceinline__ uint32_t pk(float x, float y) {
    __nv_bfloat162 h = __floats2bfloat162_rn(x, y);
    return *reinterpret_cast<uint32_t*>(&h);
}

__device__ __forceinline__ void cp16(uint32_t dst, const void* src) {
    asm volatile("cp.async.cg.shared.global [%0], [%1], 16;" :: "r"(dst), "l"(src));
}
__device__ __forceinline__ void cp_commit() {
    asm volatile("cp.async.commit_group;");
}

__device__ __forceinline__ void ldsm4(uint32_t* r, uint32_t addr) {
    asm volatile("ldmatrix.sync.aligned.m8n8.x4.shared.b16 {%0,%1,%2,%3}, [%4];"
                 : "=r"(r[0]), "=r"(r[1]), "=r"(r[2]), "=r"(r[3]) : "r"(addr));
}
__device__ __forceinline__ void ldsm4t(uint32_t* r, uint32_t addr) {
    asm volatile("ldmatrix.sync.aligned.m8n8.x4.trans.shared.b16 {%0,%1,%2,%3}, [%4];"
                 : "=r"(r[0]), "=r"(r[1]), "=r"(r[2]), "=r"(r[3]) : "r"(addr));
}

__device__ __forceinline__ void mma_bf16(float* d, const uint32_t* a, uint32_t b0, uint32_t b1) {
    asm volatile(
        "mma.sync.aligned.m16n8k16.row.col.f32.bf16.bf16.f32 "
        "{%0,%1,%2,%3}, {%4,%5,%6,%7}, {%8,%9}, {%0,%1,%2,%3};"
        : "+f"(d[0]), "+f"(d[1]), "+f"(d[2]), "+f"(d[3])
        : "r"(a[0]), "r"(a[1]), "r"(a[2]), "r"(a[3]), "r"(b0), "r"(b1));
}

// ---------------------------------------------------------------------------
// prep kernels
// ---------------------------------------------------------------------------
__global__ void conv_x_kernel(const float* __restrict__ x) {
    int g  = blockIdx.x * 256 + threadIdx.x;
    int r  = g / 96;
    int kc = (g - r * 96) * 8;
    const float* s = x + (size_t)map_row(r) * EMB + kc;
    float4 v0 = *(const float4*)s;
    float4 v1 = *(const float4*)(s + 4);
    uint4 u;
    u.x = pk(v0.x, v0.y); u.y = pk(v0.z, v0.w);
    u.z = pk(v1.x, v1.y); u.w = pk(v1.z, v1.w);
    *(uint4*)(g_A1 + (size_t)r * EMB + kc) = u;
}

// w_qkv: old col c = h*288 + dd*3 + s  ->  new col c' = s*768 + h*96 + dd
__global__ void conv_w1_kernel(const float* __restrict__ w) {
    int g  = blockIdx.x * 256 + threadIdx.x;
    int c  = g / 96;
    int k0 = (g - c * 96) * 8;
    int h  = c / 288;
    int rm = c - h * 288;
    int dd = rm / 3;
    int s  = rm - dd * 3;
    int cp_ = s * 768 + h * 96 + dd;
    float v[8];
#pragma unroll
    for (int i = 0; i < 8; i++) v[i] = w[(size_t)(k0 + i) * QKVC + c];
    uint4 u;
    u.x = pk(v[0], v[1]); u.y = pk(v[2], v[3]);
    u.z = pk(v[4], v[5]); u.w = pk(v[6], v[7]);
    *(uint4*)(g_W1 + (size_t)cp_ * EMB + k0) = u;
}

__global__ void conv_b1_kernel(const float* __restrict__ b) {
    int c = blockIdx.x * 256 + threadIdx.x;
    int h  = c / 288;
    int rm = c - h * 288;
    int dd = rm / 3;
    int s  = rm - dd * 3;
    g_b1p[s * 768 + h * 96 + dd] = b[c];
}

__global__ void conv_w2_kernel(const float* __restrict__ w) {
    int g  = blockIdx.x * 256 + threadIdx.x;
    int c  = g / 96;
    int k0 = (g - c * 96) * 8;
    float v[8];
#pragma unroll
    for (int i = 0; i < 8; i++) v[i] = w[(size_t)(k0 + i) * EMB + c];
    uint4 u;
    u.x = pk(v[0], v[1]); u.y = pk(v[2], v[3]);
    u.z = pk(v[4], v[5]); u.w = pk(v[6], v[7]);
    *(uint4*)(g_W2 + (size_t)c * EMB + k0) = u;
}

// ---------------------------------------------------------------------------
// bf16 GEMM mainloop: C[128m x 256n] = A[128,K=768] @ B[256,K]^T
// 256 threads, 8 warps of 64x64. BK=64, 4-stage cp.async, ONE sync/iter.
// ---------------------------------------------------------------------------
#define STG 49152
#define GSMEM (4 * STG)

__device__ __forceinline__ void g_fill(uint32_t sb, int stage,
                                       const __nv_bfloat16* __restrict__ A,
                                       const __nv_bfloat16* __restrict__ B,
                                       int m0, int n0, int kc, int tid) {
    uint32_t abase = sb + stage * STG;
    uint32_t bbase = abase + 16384;
#pragma unroll
    for (int i = 0; i < 4; i++) {
        int idx = tid + i * 256;             // 0..1023
        int r = idx >> 3, c = idx & 7;
        uint32_t sw = (uint32_t)(r * 128 + ((c ^ (r & 7)) << 4));
        cp16(abase + sw, A + (size_t)(m0 + r) * EMB + kc + c * 8);
    }
#pragma unroll
    for (int i = 0; i < 8; i++) {
        int idx = tid + i * 256;             // 0..2047
        int r = idx >> 3, c = idx & 7;
        uint32_t sw = (uint32_t)(r * 128 + ((c ^ (r & 7)) << 4));
        cp16(bbase + sw, B + (size_t)(n0 + r) * EMB + kc + c * 8);
    }
}

__device__ __forceinline__ void gemm_main(const __nv_bfloat16* __restrict__ A,
                                          const __nv_bfloat16* __restrict__ B,
                                          int m0, int n0,
                                          float (&acc)[4][8][4]) {
    extern __shared__ __align__(16) char dsm[];
    const uint32_t sb = (uint32_t)__cvta_generic_to_shared(dsm);
    const int tid = threadIdx.x;

#pragma unroll
    for (int i = 0; i < 4; i++)
#pragma unroll
        for (int j = 0; j < 8; j++)
#pragma unroll
            for (int q = 0; q < 4; q++) acc[i][j][q] = 0.f;

    const int wid = tid >> 5, lane = tid & 31;
    const int wm = (wid >> 2) * 64;
    const int wn = (wid & 3) * 64;
    const int lr = lane & 15, khalf = lane >> 4;

    g_fill(sb, 0, A, B, m0, n0, 0, tid);   cp_commit();
    g_fill(sb, 1, A, B, m0, n0, 64, tid);  cp_commit();
    g_fill(sb, 2, A, B, m0, n0, 128, tid); cp_commit();

#pragma unroll 1
    for (int it = 0; it < 12; it++) {
        asm volatile("cp.async.wait_group 2;");
        __syncthreads();      // stage it%4 ready AND all warps done with it-1
        if (it + 3 < 12) g_fill(sb, (it + 3) & 3, A, B, m0, n0, (it + 3) * 64, tid);
        cp_commit();          // commit every iter (keeps group accounting exact)
        const int st = it & 3;
        const uint32_t abase = sb + st * STG;
        const uint32_t bbase = abase + 16384;
#pragma unroll
        for (int kk = 0; kk < 4; kk++) {
            uint32_t a[4][4], b[4][4];
            const int kc = kk * 2 + khalf;
#pragma unroll
            for (int mf = 0; mf < 4; mf++) {
                int r = wm + mf * 16 + lr;
                ldsm4(a[mf], abase + (uint32_t)(r * 128 + ((kc ^ (r & 7)) << 4)));
            }
#pragma unroll
            for (int nt = 0; nt < 4; nt++) {
                int r = wn + nt * 16 + lr;
                ldsm4(b[nt], bbase + (uint32_t)(r * 128 + ((kc ^ (r & 7)) << 4)));
            }
#pragma unroll
            for (int mf = 0; mf < 4; mf++)
#pragma unroll
                for (int nt = 0; nt < 4; nt++) {
                    mma_bf16(acc[mf][nt * 2],     a[mf], b[nt][0], b[nt][2]);
                    mma_bf16(acc[mf][nt * 2 + 1], a[mf], b[nt][1], b[nt][3]);
                }
        }
    }
}

// ---------------------------------------------------------------------------
// GEMM 1: qkv = g_A1 @ g_W1^T + b1p -> bf16 Q/K/V [wh][t][d]
// ---------------------------------------------------------------------------
__global__ void __launch_bounds__(256, 1)
gemm1_kernel() {
    const int m0 = blockIdx.y * 128;
    const int n0 = blockIdx.x * 256;
    float acc[4][8][4];
    gemm_main(g_A1, g_W1, m0, n0, acc);

    const int tid = threadIdx.x, wid = tid >> 5, lane = tid & 31;
    const int wm = (wid >> 2) * 64, wn = (wid & 3) * 64;
    const int gid = lane >> 2, tig = lane & 3;

#pragma unroll
    for (int mf = 0; mf < 4; mf++) {
#pragma unroll
        for (int q2 = 0; q2 < 2; q2++) {
            const int r = m0 + wm + mf * 16 + gid + q2 * 8;
            const int win = r / NTOK;
            const int t = r - win * NTOK;
#pragma unroll
            for (int nf = 0; nf < 8; nf++) {
                const int c = n0 + wn + nf * 8 + tig * 2;
                const int s  = c / 768;
                const int rm = c - s * 768;
                const int h  = rm / 96;
                const int dd = rm - h * 96;
                float v0 = acc[mf][nf][q2 * 2]     + g_b1p[c];
                float v1 = acc[mf][nf][q2 * 2 + 1] + g_b1p[c + 1];
                __nv_bfloat16* base = (s == 0 ? g_Qb : (s == 1 ? g_Kb : g_Vb))
                                      + ((size_t)(win * NH + h) * NTOK + t) * HD + dd;
                *(uint32_t*)base = pk(v0, v1);
            }
        }
    }
}

// ---------------------------------------------------------------------------
// GEMM 3: out = window_reverse(g_Ob @ g_W2^T + b_proj) + x
// ---------------------------------------------------------------------------
__global__ void __launch_bounds__(256, 1)
gemm3_kernel(const float* __restrict__ x,
             const float* __restrict__ bias,
             float* __restrict__ out) {
    const int m0 = blockIdx.y * 128;
    const int n0 = blockIdx.x * 256;
    float acc[4][8][4];
    gemm_main(g_Ob, g_W2, m0, n0, acc);

    const int tid = threadIdx.x, wid = tid >> 5, lane = tid & 31;
    const int wm = (wid >> 2) * 64, wn = (wid & 3) * 64;
    const int gid = lane >> 2, tig = lane & 3;

#pragma unroll
    for (int mf = 0; mf < 4; mf++) {
#pragma unroll
        for (int q2 = 0; q2 < 2; q2++) {
            const int r = m0 + wm + mf * 16 + gid + q2 * 8;
            const int xr = map_row(r);
#pragma unroll
            for (int nf = 0; nf < 8; nf++) {
                const int c = n0 + wn + nf * 8 + tig * 2;
                const size_t idx = (size_t)xr * EMB + c;
                float2 xv = *(const float2*)(x + idx);
                out[idx]     = acc[mf][nf][q2 * 2]     + bias[c]     + xv.x;
                out[idx + 1] = acc[mf][nf][q2 * 2 + 1] + bias[c + 1] + xv.y;
            }
        }
    }
}

// ---------------------------------------------------------------------------
// Attention: grid (2048, 2). CTA = 128 threads (4 warps x 32 query rows),
// half = blockIdx.y selects rows [half*128, half*128+128). 2 CTAs/SM.
// smem: K + V only (224 rows x 208B each). Q frags loaded direct from gmem.
// ---------------------------------------------------------------------------
#define KVSTRIDE 208
#define KV_BYTES (224 * KVSTRIDE)   // 46592

__global__ void __launch_bounds__(128, 2)
attn_kernel() {
    extern __shared__ __align__(16) char smem[];
    const int wh   = blockIdx.x;
    const int half = blockIdx.y;
    const int tid  = threadIdx.x;
    const uint32_t sb = (uint32_t)__cvta_generic_to_shared(smem);
    const uint32_t Ko = sb, Vo = sb + KV_BYTES;

    const __nv_bfloat16* gq = g_Qb + (size_t)wh * NTOK * HD;
    const __nv_bfloat16* gk = g_Kb + (size_t)wh * NTOK * HD;
    const __nv_bfloat16* gv = g_Vb + (size_t)wh * NTOK * HD;

    // stage K, V (196 rows x 12 16B chunks)
    for (int i = tid; i < NTOK * 12; i += 128) {
        int t = i / 12, c = i - t * 12;
        uint32_t off = (uint32_t)(t * KVSTRIDE + c * 16);
        const size_t g = (size_t)t * HD + c * 8;
        cp16(Ko + off, gk + g);
        cp16(Vo + off, gv + g);
    }
    cp_commit();
    // zero pad rows 196..223 (12 chunks used by ldsm)
    for (int i = tid; i < 28 * 12; i += 128) {
        int t = 196 + i / 12, c = i - (i / 12) * 12;
        uint32_t off = (uint32_t)(t * KVSTRIDE + c * 16);
        uint4 z = make_uint4(0, 0, 0, 0);
        *(uint4*)(smem + off) = z;
        *(uint4*)(smem + KV_BYTES + off) = z;
    }

    const int w = tid >> 5;
    const int lane = tid & 31;
    const int gid = lane >> 2, tig = lane & 3;
    const int m0 = half * 128 + w * 32;

    // Q A-fragments direct from gmem (overlaps the cp.async staging)
    uint32_t aq[2][6][4];
    if (m0 < NTOK) {
#pragma unroll
        for (int mt = 0; mt < 2; mt++) {
            const int r0 = m0 + mt * 16 + gid;
            const int r1 = r0 + 8;
#pragma unroll
            for (int kk = 0; kk < 6; kk++) {
                const int col = kk * 16 + tig * 2;
                aq[mt][kk][0] = (r0 < NTOK) ? *(const uint32_t*)(gq + (size_t)r0 * HD + col) : 0u;
                aq[mt][kk][1] = (r1 < NTOK) ? *(const uint32_t*)(gq + (size_t)r1 * HD + col) : 0u;
                aq[mt][kk][2] = (r0 < NTOK) ? *(const uint32_t*)(gq + (size_t)r0 * HD + col + 8) : 0u;
                aq[mt][kk][3] = (r1 < NTOK) ? *(const uint32_t*)(gq + (size_t)r1 * HD + col + 8) : 0u;
            }
        }
    }

    asm volatile("cp.async.wait_group 0;");
    __syncthreads();

    if (m0 >= NTOK) return;   // fully-pad warp: after the one barrier, safe to exit

    float accO[2][12][4];
#pragma unroll
    for (int mt = 0; mt < 2; mt++)
#pragma unroll
        for (int nt = 0; nt < 12; nt++)
#pragma unroll
            for (int q = 0; q < 4; q++) accO[mt][nt][q] = 0.f;

    float rm[2][2] = {{-1e30f, -1e30f}, {-1e30f, -1e30f}};
    float rl[2][2] = {{0.f, 0.f}, {0.f, 0.f}};

#pragma unroll 1
    for (int ch = 0; ch < 7; ch++) {
        const int n0 = ch * 32;
        float s[2][4][4];
#pragma unroll
        for (int mt = 0; mt < 2; mt++)
#pragma unroll
            for (int nt = 0; nt < 4; nt++)
#pragma unroll
                for (int q = 0; q < 4; q++) s[mt][nt][q] = 0.f;

#pragma unroll
        for (int kk = 0; kk < 6; kk++) {
            uint32_t kb0[4], kb1[4];
            uint32_t kaddr = Ko + (uint32_t)((n0 + (lane & 7) + ((lane >> 4) << 3)) * KVSTRIDE
                                             + (kk * 2 + ((lane >> 3) & 1)) * 16);
            ldsm4(kb0, kaddr);
            ldsm4(kb1, kaddr + 16 * KVSTRIDE);
#pragma unroll
            for (int mt = 0; mt < 2; mt++) {
                mma_bf16(s[mt][0], aq[mt][kk], kb0[0], kb0[1]);
                mma_bf16(s[mt][1], aq[mt][kk], kb0[2], kb0[3]);
                mma_bf16(s[mt][2], aq[mt][kk], kb1[0], kb1[1]);
                mma_bf16(s[mt][3], aq[mt][kk], kb1[2], kb1[3]);
            }
        }

        if (ch == 6) {
#pragma unroll
            for (int mt = 0; mt < 2; mt++)
#pragma unroll
                for (int nt = 0; nt < 4; nt++)
#pragma unroll
                    for (int q = 0; q < 4; q++) {
                        int col = n0 + nt * 8 + tig * 2 + (q & 1);
                        if (col >= NTOK) s[mt][nt][q] = -1e30f;
                    }
        }

#pragma unroll
        for (int mt = 0; mt < 2; mt++) {
#pragma unroll
            for (int hf = 0; hf < 2; hf++) {
                float mx = -1e30f;
#pragma unroll
                for (int nt = 0; nt < 4; nt++) {
                    mx = fmaxf(mx, s[mt][nt][hf * 2]);
                    mx = fmaxf(mx, s[mt][nt][hf * 2 + 1]);
                }
                mx = fmaxf(mx, __shfl_xor_sync(0xffffffff, mx, 1));
                mx = fmaxf(mx, __shfl_xor_sync(0xffffffff, mx, 2));
                float mn = fmaxf(rm[mt][hf], mx);
                float sc = __expf(rm[mt][hf] - mn);
                rm[mt][hf] = mn;
                float ls = 0.f;
#pragma unroll
                for (int nt = 0; nt < 4; nt++) {
                    float p0 = __expf(s[mt][nt][hf * 2] - mn);
                    float p1 = __expf(s[mt][nt][hf * 2 + 1] - mn);
                    s[mt][nt][hf * 2] = p0;
                    s[mt][nt][hf * 2 + 1] = p1;
                    ls += p0 + p1;
                }
                ls += __shfl_xor_sync(0xffffffff, ls, 1);
                ls += __shfl_xor_sync(0xffffffff, ls, 2);
                rl[mt][hf] = rl[mt][hf] * sc + ls;
#pragma unroll
                for (int nt = 0; nt < 12; nt++) {
                    accO[mt][nt][hf * 2]     *= sc;
                    accO[mt][nt][hf * 2 + 1] *= sc;
                }
            }
        }

#pragma unroll
        for (int kk = 0; kk < 2; kk++) {
            uint32_t ap[2][4];
#pragma unroll
            for (int mt = 0; mt < 2; mt++) {
                ap[mt][0] = pk(s[mt][kk * 2][0], s[mt][kk * 2][1]);
                ap[mt][1] = pk(s[mt][kk * 2][2], s[mt][kk * 2][3]);
                ap[mt][2] = pk(s[mt][kk * 2 + 1][0], s[mt][kk * 2 + 1][1]);
                ap[mt][3] = pk(s[mt][kk * 2 + 1][2], s[mt][kk * 2 + 1][3]);
            }
#pragma unroll
            for (int u = 0; u < 6; u++) {
                uint32_t vb[4];
                ldsm4t(vb, Vo + (uint32_t)((n0 + kk * 16 + (lane & 7) + (((lane >> 3) & 1) << 3)) * KVSTRIDE
                                           + (u * 2 + (lane >> 4)) * 16));
#pragma unroll
                for (int mt = 0; mt < 2; mt++) {
                    mma_bf16(accO[mt][u * 2],     ap[mt], vb[0], vb[1]);
                    mma_bf16(accO[mt][u * 2 + 1], ap[mt], vb[2], vb[3]);
                }
            }
        }
    }

    const int win = wh >> 3;
    const int h   = wh & 7;
#pragma unroll
    for (int mt = 0; mt < 2; mt++) {
#pragma unroll
        for (int hf = 0; hf < 2; hf++) {
            const int t = m0 + mt * 16 + gid + hf * 8;
            if (t < NTOK) {
                const float inv = 1.0f / (rl[mt][hf] * 27.712812921102035f);
                uint32_t* op = (uint32_t*)(g_Ob + ((size_t)(win * NTOK + t)) * EMB
                                           + h * HD + tig * 2);
#pragma unroll
                for (int nt = 0; nt < 12; nt++) {
                    op[nt * 4] = pk(accO[mt][nt][hf * 2] * inv,
                                    accO[mt][nt][hf * 2 + 1] * inv);
                }
            }
        }
    }
}

// ---------------------------------------------------------------------------
extern "C" void kernel_launch(void* const* d_in, const int* in_sizes, int n_in,
                              void* d_out, int out_size) {
    const float* x      = (const float*)d_in[0];
    const float* w_qkv  = (const float*)d_in[1];
    const float* b_qkv  = (const float*)d_in[2];
    const float* w_proj = (const float*)d_in[3];
    const float* b_proj = (const float*)d_in[4];
    float* out = (float*)d_out;

    conv_x_kernel<<<MROWS * 96 / 256, 256>>>(x);
    conv_w1_kernel<<<QKVC * 96 / 256, 256>>>(w_qkv);
    conv_b1_kernel<<<QKVC / 256, 256>>>(b_qkv);
    conv_w2_kernel<<<EMB * 96 / 256, 256>>>(w_proj);

    cudaFuncSetAttribute(gemm1_kernel, cudaFuncAttributeMaxDynamicSharedMemorySize, GSMEM);
    gemm1_kernel<<<dim3(QKVC / 256, MROWS / 128), 256, GSMEM>>>();

    const int asmem = 2 * KV_BYTES;   // 93184
    cudaFuncSetAttribute(attn_kernel, cudaFuncAttributeMaxDynamicSharedMemorySize, asmem);
    attn_kernel<<<dim3(NWIN * NH, 2), 128, asmem>>>();

    cudaFuncSetAttribute(gemm3_kernel, cudaFuncAttributeMaxDynamicSharedMemorySize, GSMEM);
    gemm3_kernel<<<dim3(EMB / 256, MROWS / 128), 256, GSMEM>>>(x, b_proj, out);
}